// round 3
// baseline (speedup 1.0000x reference)
#include <cuda_runtime.h>
#include <cuda_bf16.h>
#include <cstdint>

#define NROWS 4096
#define DDIM  1024
#define NKEY  65536
#define KSEL  32

// Scratch (static device arrays: allocation-guard safe; referenced directly
// from device code so kernel_launch stays pure kernel-launches)
__device__ float g_q[(size_t)NROWS * DDIM];          // 16 MB
__device__ float g_scores[(size_t)NROWS * NKEY];     // 1 GiB

// ---------------------------------------------------------------------------
// Packed f32x2 helpers (sm_103a: FFMA-3reg is rt=2/SMSP; f32x2 doubles tput)
// ---------------------------------------------------------------------------
__device__ __forceinline__ unsigned long long bcast2(float a) {
    unsigned long long r;
    unsigned int ai = __float_as_uint(a);
    asm("mov.b64 %0, {%1, %1};" : "=l"(r) : "r"(ai));
    return r;
}
__device__ __forceinline__ void fma2(unsigned long long& d,
                                     unsigned long long a,
                                     unsigned long long b) {
    asm("fma.rn.f32x2 %0, %1, %2, %0;" : "+l"(d) : "l"(a), "l"(b));
}

// ---------------------------------------------------------------------------
// NT GEMM: C[m,n] = sum_k A[m,k]*B[n,k]; A: MxK row-major, B: NxK row-major
// BM=BN=128, BK=16, 256 threads, 8x8 per thread (f32x2-packed along n)
// Mode 0 (QPROJ):  A=x(param),  B=q_w(param), C=g_q
// Mode 1 (SCORES): A=g_q,       B=keys(param), C=g_scores
// ---------------------------------------------------------------------------
#define BM 128
#define BN 128
#define BK 16

template <int MODE>
__global__ __launch_bounds__(256) void gemm_nt_kernel(
    const float* __restrict__ Ain, const float* __restrict__ B,
    int M, int N, int K)
{
    const float* __restrict__ A = (MODE == 0) ? Ain : (const float*)g_q;
    float* __restrict__ C = (MODE == 0) ? (float*)g_q : (float*)g_scores;

    __shared__ __align__(16) float As[BK][BM];
    __shared__ __align__(16) float Bs[BK][BN];
    const int tid = threadIdx.x;
    const int tx = tid & 15;   // 0..15 -> n
    const int ty = tid >> 4;   // 0..15 -> m
    const int m0 = blockIdx.x * BM;
    const int n0 = blockIdx.y * BN;

    unsigned long long acc[8][4];
    #pragma unroll
    for (int i = 0; i < 8; i++)
        #pragma unroll
        for (int j = 0; j < 4; j++) acc[i][j] = 0ull;  // two packed 0.0f

    for (int kt = 0; kt < K; kt += BK) {
        #pragma unroll
        for (int p = 0; p < 2; p++) {
            int i = tid + p * 256;
            int row = i >> 2;
            int kq  = (i & 3) << 2;
            float4 av = *reinterpret_cast<const float4*>(
                &A[(size_t)(m0 + row) * K + kt + kq]);
            As[kq + 0][row] = av.x; As[kq + 1][row] = av.y;
            As[kq + 2][row] = av.z; As[kq + 3][row] = av.w;
            float4 bv = *reinterpret_cast<const float4*>(
                &B[(size_t)(n0 + row) * K + kt + kq]);
            Bs[kq + 0][row] = bv.x; Bs[kq + 1][row] = bv.y;
            Bs[kq + 2][row] = bv.z; Bs[kq + 3][row] = bv.w;
        }
        __syncthreads();
        #pragma unroll
        for (int k = 0; k < BK; k++) {
            float a[8];
            *reinterpret_cast<float4*>(&a[0]) =
                *reinterpret_cast<const float4*>(&As[k][ty * 4]);
            *reinterpret_cast<float4*>(&a[4]) =
                *reinterpret_cast<const float4*>(&As[k][ty * 4 + 64]);
            ulonglong2 b01 = *reinterpret_cast<const ulonglong2*>(&Bs[k][tx * 4]);
            ulonglong2 b23 = *reinterpret_cast<const ulonglong2*>(&Bs[k][tx * 4 + 64]);
            #pragma unroll
            for (int i = 0; i < 8; i++) {
                unsigned long long ab = bcast2(a[i]);
                fma2(acc[i][0], ab, b01.x);
                fma2(acc[i][1], ab, b01.y);
                fma2(acc[i][2], ab, b23.x);
                fma2(acc[i][3], ab, b23.y);
            }
        }
        __syncthreads();
    }

    #pragma unroll
    for (int i = 0; i < 8; i++) {
        int m = m0 + ty * 4 + (i < 4 ? i : 60 + i);  // i>=4 -> +64 + (i-4)
        float2 c0 = *reinterpret_cast<float2*>(&acc[i][0]);
        float2 c1 = *reinterpret_cast<float2*>(&acc[i][1]);
        float2 c2 = *reinterpret_cast<float2*>(&acc[i][2]);
        float2 c3 = *reinterpret_cast<float2*>(&acc[i][3]);
        *reinterpret_cast<float4*>(&C[(size_t)m * N + n0 + tx * 4]) =
            make_float4(c0.x, c0.y, c1.x, c1.y);
        *reinterpret_cast<float4*>(&C[(size_t)m * N + n0 + 64 + tx * 4]) =
            make_float4(c2.x, c2.y, c3.x, c3.y);
    }
}

// ---------------------------------------------------------------------------
// Per-row: exact top-32 over 65536 scores -> softmax -> weighted values gather
// One CTA (128 thr) per row. Static shared only: 4096 floats + 4096 u16 = 24KB.
// ---------------------------------------------------------------------------
__global__ __launch_bounds__(128) void topk_out_kernel(
    const float* __restrict__ values, float* __restrict__ out)
{
    __shared__ float          sv[4096];
    __shared__ unsigned short si[4096];
    __shared__ float rwv[4];
    __shared__ int   rws[4];
    __shared__ float wv[KSEL];
    __shared__ int   wi[KSEL];
    __shared__ float sw[KSEL];
    __shared__ float sZ;

    const int tid = threadIdx.x;
    const int row = blockIdx.x;
    const float* s = (const float*)g_scores + (size_t)row * NKEY;

    // per-thread exact top-32 (ascending), static indices only (no spills)
    float lv[KSEL];
    int   li[KSEL];
    #pragma unroll
    for (int j = 0; j < KSEL; j++) { lv[j] = -INFINITY; li[j] = 0; }

    for (int i = tid; i < NKEY; i += 128) {
        float v = s[i];
        if (v > lv[0]) {
            #pragma unroll
            for (int j = 0; j < KSEL; j++) {
                float nxt  = (j < KSEL - 1) ? lv[j + 1] : INFINITY;
                int   nxti = (j < KSEL - 1) ? li[j + 1] : 0;
                if (nxt <= v)        { lv[j] = nxt; li[j] = nxti; }
                else if (lv[j] <= v) { lv[j] = v;   li[j] = i;    }
            }
        }
    }

    // dump candidates (conflict-free: slot = j*128 + tid)
    #pragma unroll
    for (int j = 0; j < KSEL; j++) {
        sv[j * 128 + tid] = lv[j];
        si[j * 128 + tid] = (unsigned short)li[j];
    }
    __syncthreads();

    // 32 x block-wide argmax extraction
    const int lane = tid & 31, warp = tid >> 5;
    for (int it = 0; it < KSEL; it++) {
        float best = -INFINITY; int bslot = 0;
        #pragma unroll 8
        for (int jj = tid; jj < 4096; jj += 128) {
            float v = sv[jj];
            if (v > best) { best = v; bslot = jj; }
        }
        #pragma unroll
        for (int o = 16; o > 0; o >>= 1) {
            float ov = __shfl_down_sync(0xffffffffu, best, o);
            int   os = __shfl_down_sync(0xffffffffu, bslot, o);
            if (ov > best) { best = ov; bslot = os; }
        }
        if (lane == 0) { rwv[warp] = best; rws[warp] = bslot; }
        __syncthreads();
        if (tid == 0) {
            float b = rwv[0]; int bs = rws[0];
            #pragma unroll
            for (int w = 1; w < 4; w++)
                if (rwv[w] > b) { b = rwv[w]; bs = rws[w]; }
            wv[it] = b;
            wi[it] = (int)si[bs];
            sv[bs] = -INFINITY;
        }
        __syncthreads();
    }

    // softmax (TEMP = 1); wv[0] is the max (extracted descending)
    if (tid < KSEL) sw[tid] = expf(wv[tid] - wv[0]);
    __syncthreads();
    if (tid == 0) {
        float z = 0.f;
        #pragma unroll
        for (int j = 0; j < KSEL; j++) z += sw[j];
        sZ = z;
    }
    __syncthreads();
    const float invZ = 1.0f / sZ;

    // weighted gather of values rows (GATING = 1)
    for (int d = tid; d < DDIM; d += 128) {
        float acc = 0.f;
        #pragma unroll 8
        for (int k = 0; k < KSEL; k++)
            acc += sw[k] * values[(size_t)wi[k] * DDIM + d];
        out[(size_t)row * DDIM + d] = acc * invZ;
    }
}

// ---------------------------------------------------------------------------
extern "C" void kernel_launch(void* const* d_in, const int* in_sizes, int n_in,
                              void* d_out, int out_size) {
    const float* x      = (const float*)d_in[0];
    const float* q_w    = (const float*)d_in[1];
    const float* keys   = (const float*)d_in[2];
    const float* values = (const float*)d_in[3];
    float* out = (float*)d_out;

    cudaStream_t st = cudaStreamPerThread;  // capture-safe stream

    // q = x @ q_w^T  (4096 x 1024 x 1024) -> g_q
    dim3 g1(NROWS / BM, DDIM / BN);
    gemm_nt_kernel<0><<<g1, 256, 0, st>>>(x, q_w, NROWS, DDIM, DDIM);

    // scores = g_q @ keys^T  (4096 x 65536 x 1024) -> g_scores
    // x-dim = m-tile fastest so a wave reuses each keys tile through L2
    dim3 g2(NROWS / BM, NKEY / BN);
    gemm_nt_kernel<1><<<g2, 256, 0, st>>>(nullptr, keys, NROWS, NKEY, DDIM);

    // fused top-32 + softmax + gather (reads g_scores)
    topk_out_kernel<<<NROWS, 128, 0, st>>>(values, out);
}

// round 8
// speedup vs baseline: 2.6189x; 2.6189x over previous
#include <cuda_runtime.h>
#include <cuda_bf16.h>
#include <cstdint>

#define NROWS 4096
#define DDIM  1024
#define NKEY  65536
#define KSEL  32
#define NCAND 48

// ---------------------------------------------------------------------------
// Static device scratch (allocation-guard safe). NEVER passed as host-side
// kernel args (host shadow trap!) — referenced from device code only.
// ---------------------------------------------------------------------------
__device__ float g_q[(size_t)NROWS * DDIM];                 // 16 MB (fp32 q)
__device__ __nv_bfloat16 g_qbf[(size_t)NROWS * DDIM];       // 8 MB
__device__ __nv_bfloat16 g_kbf[(size_t)NKEY * DDIM];        // 128 MB
__device__ __nv_bfloat16 g_sbf[(size_t)NROWS * NKEY];       // 512 MB (bf16 scores)

// ---------------------------------------------------------------------------
// Packed f32x2 helpers (qproj fp32 GEMM)
// ---------------------------------------------------------------------------
__device__ __forceinline__ unsigned long long bcast2(float a) {
    unsigned long long r;
    unsigned int ai = __float_as_uint(a);
    asm("mov.b64 %0, {%1, %1};" : "=l"(r) : "r"(ai));
    return r;
}
__device__ __forceinline__ void fma2(unsigned long long& d,
                                     unsigned long long a,
                                     unsigned long long b) {
    asm("fma.rn.f32x2 %0, %1, %2, %0;" : "+l"(d) : "l"(a), "l"(b));
}

__device__ __forceinline__ uint32_t smem_u32(const void* p) {
    uint32_t a;
    asm("{ .reg .u64 t; cvta.to.shared.u64 t, %1; cvt.u32.u64 %0, t; }"
        : "=r"(a) : "l"(p));
    return a;
}

// mma.sync / ldmatrix / cp.async (baseline ISA, valid on plain sm_103 target)
__device__ __forceinline__ void ldm_x4(uint32_t* r, uint32_t addr) {
    asm volatile("ldmatrix.sync.aligned.m8n8.x4.shared.b16 {%0,%1,%2,%3}, [%4];"
        : "=r"(r[0]), "=r"(r[1]), "=r"(r[2]), "=r"(r[3]) : "r"(addr));
}
__device__ __forceinline__ void mma_bf16(float* c, const uint32_t* a,
                                         const uint32_t* b) {
    asm volatile(
        "mma.sync.aligned.m16n8k16.row.col.f32.bf16.bf16.f32 "
        "{%0,%1,%2,%3}, {%4,%5,%6,%7}, {%8,%9}, {%0,%1,%2,%3};"
        : "+f"(c[0]), "+f"(c[1]), "+f"(c[2]), "+f"(c[3])
        : "r"(a[0]), "r"(a[1]), "r"(a[2]), "r"(a[3]), "r"(b[0]), "r"(b[1]));
}
__device__ __forceinline__ void cp16(uint32_t dst, const void* src) {
    asm volatile("cp.async.cg.shared.global [%0], [%1], 16;"
        :: "r"(dst), "l"(src));
}
__device__ __forceinline__ void cp_commit() {
    asm volatile("cp.async.commit_group;");
}
template <int N>
__device__ __forceinline__ void cp_wait() {
    asm volatile("cp.async.wait_group %0;" :: "n"(N) : "memory");
}

// ---------------------------------------------------------------------------
// qproj: g_q = x @ q_w^T (4096x1024x1024), fp32, BM=BN=128, BK=16
// ---------------------------------------------------------------------------
#define BM 128
#define BN 128
#define BK 16

__global__ __launch_bounds__(256) void gemm_qproj_kernel(
    const float* __restrict__ A, const float* __restrict__ B, int M, int N, int K)
{
    float* __restrict__ C = (float*)g_q;
    __shared__ __align__(16) float As[BK][BM];
    __shared__ __align__(16) float Bs[BK][BN];
    const int tid = threadIdx.x;
    const int tx = tid & 15;
    const int ty = tid >> 4;
    const int m0 = blockIdx.x * BM;
    const int n0 = blockIdx.y * BN;

    unsigned long long acc[8][4];
    #pragma unroll
    for (int i = 0; i < 8; i++)
        #pragma unroll
        for (int j = 0; j < 4; j++) acc[i][j] = 0ull;

    for (int kt = 0; kt < K; kt += BK) {
        #pragma unroll
        for (int p = 0; p < 2; p++) {
            int i = tid + p * 256;
            int row = i >> 2;
            int kq  = (i & 3) << 2;
            float4 av = *reinterpret_cast<const float4*>(
                &A[(size_t)(m0 + row) * K + kt + kq]);
            As[kq + 0][row] = av.x; As[kq + 1][row] = av.y;
            As[kq + 2][row] = av.z; As[kq + 3][row] = av.w;
            float4 bv = *reinterpret_cast<const float4*>(
                &B[(size_t)(n0 + row) * K + kt + kq]);
            Bs[kq + 0][row] = bv.x; Bs[kq + 1][row] = bv.y;
            Bs[kq + 2][row] = bv.z; Bs[kq + 3][row] = bv.w;
        }
        __syncthreads();
        #pragma unroll
        for (int k = 0; k < BK; k++) {
            float a[8];
            *reinterpret_cast<float4*>(&a[0]) =
                *reinterpret_cast<const float4*>(&As[k][ty * 4]);
            *reinterpret_cast<float4*>(&a[4]) =
                *reinterpret_cast<const float4*>(&As[k][ty * 4 + 64]);
            ulonglong2 b01 = *reinterpret_cast<const ulonglong2*>(&Bs[k][tx * 4]);
            ulonglong2 b23 = *reinterpret_cast<const ulonglong2*>(&Bs[k][tx * 4 + 64]);
            #pragma unroll
            for (int i = 0; i < 8; i++) {
                unsigned long long ab = bcast2(a[i]);
                fma2(acc[i][0], ab, b01.x);
                fma2(acc[i][1], ab, b01.y);
                fma2(acc[i][2], ab, b23.x);
                fma2(acc[i][3], ab, b23.y);
            }
        }
        __syncthreads();
    }

    #pragma unroll
    for (int i = 0; i < 8; i++) {
        int m = m0 + ty * 4 + (i < 4 ? i : 60 + i);
        float2 c0 = *reinterpret_cast<float2*>(&acc[i][0]);
        float2 c1 = *reinterpret_cast<float2*>(&acc[i][1]);
        float2 c2 = *reinterpret_cast<float2*>(&acc[i][2]);
        float2 c3 = *reinterpret_cast<float2*>(&acc[i][3]);
        *reinterpret_cast<float4*>(&C[(size_t)m * N + n0 + tx * 4]) =
            make_float4(c0.x, c0.y, c1.x, c1.y);
        *reinterpret_cast<float4*>(&C[(size_t)m * N + n0 + 64 + tx * 4]) =
            make_float4(c2.x, c2.y, c3.x, c3.y);
    }
}

// ---------------------------------------------------------------------------
// fp32 -> bf16 conversion. MODE 0: g_q -> g_qbf. MODE 1: keys(param) -> g_kbf.
// ---------------------------------------------------------------------------
template <int MODE>
__global__ __launch_bounds__(256) void cvt_bf16_kernel(const float* __restrict__ srcIn)
{
    const float* __restrict__ src = (MODE == 0) ? (const float*)g_q : srcIn;
    __nv_bfloat16* __restrict__ dst = (MODE == 0) ? (__nv_bfloat16*)g_qbf
                                                  : (__nv_bfloat16*)g_kbf;
    size_t i = (size_t)blockIdx.x * 256 + threadIdx.x;   // float4 index
    float4 v = reinterpret_cast<const float4*>(src)[i];
    __nv_bfloat162 p0 = __floats2bfloat162_rn(v.x, v.y);
    __nv_bfloat162 p1 = __floats2bfloat162_rn(v.z, v.w);
    __nv_bfloat162* dp = reinterpret_cast<__nv_bfloat162*>(dst) + 2 * i;
    dp[0] = p0; dp[1] = p1;
}

// ---------------------------------------------------------------------------
// approx scores = q_bf @ keys_bf^T via mma.sync (single bf16 term) -> bf16
// Tile 128x128, BK=16, 8 warps (2x4 -> each 64x32), 4-stage cp.async ring.
// smem rows padded to 24 bf16 (48B) -> conflict-free ldmatrix. 48KB smem.
// ---------------------------------------------------------------------------
#define SROW 24
#define STAGE_E (128 * SROW)          // elems per stage per array
#define NSTG 4

__global__ __launch_bounds__(256) void scores_mma_kernel()
{
    __shared__ __align__(16) __nv_bfloat16 sA[NSTG * STAGE_E];   // 24 KB
    __shared__ __align__(16) __nv_bfloat16 sB[NSTG * STAGE_E];   // 24 KB

    const int tid = threadIdx.x;
    const int wid = tid >> 5;
    const int lid = tid & 31;
    const int m0 = blockIdx.x * 128;
    const int n0 = blockIdx.y * 128;

    const int base_m = (wid & 1) * 64;
    const int base_n = (wid >> 1) * 32;

    const uint32_t aA = smem_u32(sA), aB = smem_u32(sB);
    const uint32_t STB = STAGE_E * 2;  // 6144 bytes

    const int ldrow = tid >> 1;
    const int ldch  = tid & 1;
    const uint32_t dOff = ldrow * 48 + ldch * 16;
    const size_t gA = (size_t)(m0 + ldrow) * DDIM + ldch * 8;
    const size_t gB = (size_t)(n0 + ldrow) * DDIM + ldch * 8;

    const uint32_t aOff = (uint32_t)(base_m + (lid & 7) + ((lid >> 3) & 1) * 8) * 48
                        + (uint32_t)(lid >> 4) * 16;
    const uint32_t bOff = (uint32_t)(base_n + (lid & 7) + ((lid >= 16) ? 8 : 0)) * 48
                        + (uint32_t)((lid >> 3) & 1) * 16;

    float c[4][4][4];
    #pragma unroll
    for (int i = 0; i < 4; i++)
        #pragma unroll
        for (int j = 0; j < 4; j++)
            #pragma unroll
            for (int k = 0; k < 4; k++) c[i][j][k] = 0.f;

    const int NKT = DDIM / 16;  // 64

    #pragma unroll
    for (int s = 0; s < NSTG - 1; s++) {
        cp16(aA + s * STB + dOff, (const char*)g_qbf + (gA + (size_t)s * 16) * 2);
        cp16(aB + s * STB + dOff, (const char*)g_kbf + (gB + (size_t)s * 16) * 2);
        cp_commit();
    }

    for (int kt = 0; kt < NKT; kt++) {
        if (kt + NSTG - 1 < NKT) {
            const uint32_t so = ((kt + NSTG - 1) & (NSTG - 1)) * STB;
            const size_t ko = (size_t)(kt + NSTG - 1) * 16;
            cp16(aA + so + dOff, (const char*)g_qbf + (gA + ko) * 2);
            cp16(aB + so + dOff, (const char*)g_kbf + (gB + ko) * 2);
        }
        cp_commit();
        cp_wait<NSTG - 1>();
        __syncthreads();

        const uint32_t so = (kt & (NSTG - 1)) * STB;
        uint32_t ah[4][4], bh[2][4];
        #pragma unroll
        for (int mf = 0; mf < 4; mf++)
            ldm_x4(ah[mf], aA + so + aOff + mf * (16 * 48));
        #pragma unroll
        for (int np = 0; np < 2; np++)
            ldm_x4(bh[np], aB + so + bOff + np * (16 * 48));
        #pragma unroll
        for (int mf = 0; mf < 4; mf++)
            #pragma unroll
            for (int nf = 0; nf < 4; nf++)
                mma_bf16(c[mf][nf], ah[mf], &bh[nf >> 1][(nf & 1) * 2]);
        __syncthreads();
    }

    const int crow = lid >> 2;
    const int ccol = (lid & 3) * 2;
    #pragma unroll
    for (int mf = 0; mf < 4; mf++) {
        #pragma unroll
        for (int nf = 0; nf < 4; nf++) {
            int m = m0 + base_m + mf * 16 + crow;
            int n = n0 + base_n + nf * 8 + ccol;
            *reinterpret_cast<__nv_bfloat162*>(&g_sbf[(size_t)m * NKEY + n]) =
                __floats2bfloat162_rn(c[mf][nf][0], c[mf][nf][1]);
            *reinterpret_cast<__nv_bfloat162*>(&g_sbf[(size_t)(m + 8) * NKEY + n]) =
                __floats2bfloat162_rn(c[mf][nf][2], c[mf][nf][3]);
        }
    }
}

// ---------------------------------------------------------------------------
// Per-row: approx top-48 candidates -> BIT-EXACT R3-style fp32 rescore
// (sequential fma chain, k ascending — reproduces the validated R3 scores
// bit-for-bit so boundary near-ties resolve exactly as the passing run did)
// -> exact rank (JAX lowest-index tie-break) -> softmax -> weighted gather.
// ---------------------------------------------------------------------------
__global__ __launch_bounds__(128) void topk_out_kernel(
    const float* __restrict__ keys, const float* __restrict__ values,
    float* __restrict__ out)
{
    __shared__ float          sv[4096];
    __shared__ unsigned short si[4096];
    __shared__ __align__(16) float qrow[DDIM];
    __shared__ float rwv[4];
    __shared__ int   rws[4];
    __shared__ int   ci[NCAND];
    __shared__ float rs[NCAND];
    __shared__ int   sidx[KSEL];
    __shared__ float ssc[KSEL];
    __shared__ float sw[KSEL];
    __shared__ float sZ;

    const int tid = threadIdx.x;
    const int row = blockIdx.x;
    const __nv_bfloat16* srow = (const __nv_bfloat16*)g_sbf + (size_t)row * NKEY;

    // load q row (fp32) for rescoring
    #pragma unroll
    for (int j = tid; j < DDIM / 4; j += 128)
        reinterpret_cast<float4*>(qrow)[j] =
            reinterpret_cast<const float4*>((const float*)g_q + (size_t)row * DDIM)[j];

    // per-thread top-32 of approx scores (vectorized bf16x8 loads)
    float lv[KSEL];
    int   li[KSEL];
    #pragma unroll
    for (int j = 0; j < KSEL; j++) { lv[j] = -INFINITY; li[j] = 0; }

    for (int it = 0; it < NKEY / (128 * 8); it++) {
        int vec = it * 128 + tid;
        uint4 raw = reinterpret_cast<const uint4*>(srow)[vec];
        int base = vec * 8;
        uint32_t ws[4] = {raw.x, raw.y, raw.z, raw.w};
        #pragma unroll
        for (int h = 0; h < 4; h++) {
            #pragma unroll
            for (int e = 0; e < 2; e++) {
                float v = __uint_as_float(e == 0 ? (ws[h] << 16)
                                                 : (ws[h] & 0xffff0000u));
                int idx = base + h * 2 + e;
                if (v > lv[0]) {
                    #pragma unroll
                    for (int j = 0; j < KSEL; j++) {
                        float nxt  = (j < KSEL - 1) ? lv[j + 1] : INFINITY;
                        int   nxti = (j < KSEL - 1) ? li[j + 1] : 0;
                        if (nxt <= v)        { lv[j] = nxt; li[j] = nxti; }
                        else if (lv[j] <= v) { lv[j] = v;   li[j] = idx;  }
                    }
                }
            }
        }
    }

    #pragma unroll
    for (int j = 0; j < KSEL; j++) {
        sv[j * 128 + tid] = lv[j];
        si[j * 128 + tid] = (unsigned short)li[j];
    }
    __syncthreads();

    // extract 48 candidates by block-wide argmax
    const int lane = tid & 31, warp = tid >> 5;
    for (int it = 0; it < NCAND; it++) {
        float best = -INFINITY; int bslot = 0;
        #pragma unroll 8
        for (int jj = tid; jj < 4096; jj += 128) {
            float v = sv[jj];
            if (v > best) { best = v; bslot = jj; }
        }
        #pragma unroll
        for (int o = 16; o > 0; o >>= 1) {
            float ov = __shfl_down_sync(0xffffffffu, best, o);
            int   os = __shfl_down_sync(0xffffffffu, bslot, o);
            if (ov > best) { best = ov; bslot = os; }
        }
        if (lane == 0) { rwv[warp] = best; rws[warp] = bslot; }
        __syncthreads();
        if (tid == 0) {
            float b = rwv[0]; int bs = rws[0];
            #pragma unroll
            for (int w = 1; w < 4; w++)
                if (rwv[w] > b) { b = rwv[w]; bs = rws[w]; }
            ci[it] = (int)si[bs];
            sv[bs] = -INFINITY;
        }
        __syncthreads();
    }

    // BIT-EXACT rescore: one thread per candidate, sequential rn-fma chain
    // over k = 0..1023 (identical rounding order to the validated fp32 GEMM).
    if (tid < NCAND) {
        const float* krow = keys + (size_t)ci[tid] * DDIM;
        float acc = 0.f;
        #pragma unroll 8
        for (int k = 0; k < DDIM; k++)
            acc = __fmaf_rn(qrow[k], __ldg(&krow[k]), acc);
        rs[tid] = acc;
    }
    __syncthreads();

    // exact rank with stable (lower-index-first) tie-break; select top-32
    if (tid < NCAND) {
        float sc = rs[tid];
        int   myi = ci[tid];
        int rank = 0;
        #pragma unroll
        for (int j = 0; j < NCAND; j++) {
            float sj = rs[j];
            rank += (sj > sc) || (sj == sc && ci[j] < myi);
        }
        if (rank < KSEL) { sidx[rank] = myi; ssc[rank] = sc; }
    }
    __syncthreads();

    // softmax over exact top-32 (TEMP=1); ssc[0] is the max
    if (tid < KSEL) sw[tid] = expf(ssc[tid] - ssc[0]);
    __syncthreads();
    if (tid == 0) {
        float z = 0.f;
        #pragma unroll
        for (int j = 0; j < KSEL; j++) z += sw[j];
        sZ = z;
    }
    __syncthreads();
    const float invZ = 1.0f / sZ;

    // weighted gather of values rows (GATING=1)
    for (int d = tid; d < DDIM; d += 128) {
        float acc = 0.f;
        #pragma unroll 8
        for (int k = 0; k < KSEL; k++)
            acc += sw[k] * values[(size_t)sidx[k] * DDIM + d];
        out[(size_t)row * DDIM + d] = acc * invZ;
    }
}

// ---------------------------------------------------------------------------
extern "C" void kernel_launch(void* const* d_in, const int* in_sizes, int n_in,
                              void* d_out, int out_size) {
    const float* x      = (const float*)d_in[0];
    const float* q_w    = (const float*)d_in[1];
    const float* keys   = (const float*)d_in[2];
    const float* values = (const float*)d_in[3];
    float* out = (float*)d_out;

    cudaStream_t st = cudaStreamPerThread;

    // 1) q = x @ q_w^T -> g_q (fp32)
    dim3 g1(NROWS / BM, DDIM / BN);
    gemm_qproj_kernel<<<g1, 256, 0, st>>>(x, q_w, NROWS, DDIM, DDIM);

    // 2) bf16 conversions (dst via device symbols inside kernels)
    cvt_bf16_kernel<0><<<(NROWS * DDIM / 4) / 256, 256, 0, st>>>(nullptr);
    cvt_bf16_kernel<1><<<(int)(((size_t)NKEY * DDIM / 4) / 256), 256, 0, st>>>(keys);

    // 3) approx scores via bf16 mma -> g_sbf (m fastest for L2 keys reuse)
    dim3 g2(NROWS / 128, NKEY / 128);
    scores_mma_kernel<<<g2, 256, 0, st>>>();

    // 4) candidates + bit-exact rescore + softmax + gather
    topk_out_kernel<<<NROWS, 128, 0, st>>>(keys, values, out);
}

// round 9
// speedup vs baseline: 2.9678x; 1.1333x over previous
#include <cuda_runtime.h>
#include <cuda_bf16.h>
#include <cstdint>

#define NROWS 4096
#define DDIM  1024
#define NKEY  65536
#define KSEL  32
#define NCAND 48

// ---------------------------------------------------------------------------
// Static device scratch (allocation-guard safe). NEVER passed as host-side
// kernel args (host shadow trap!) — referenced from device code only.
// ---------------------------------------------------------------------------
__device__ float g_q[(size_t)NROWS * DDIM];                 // 16 MB (fp32 q)
__device__ __nv_bfloat16 g_qbf[(size_t)NROWS * DDIM];       // 8 MB
__device__ __nv_bfloat16 g_kbf[(size_t)NKEY * DDIM];        // 128 MB
__device__ __nv_bfloat16 g_sbf[(size_t)NROWS * NKEY];       // 512 MB (bf16 scores)

// ---------------------------------------------------------------------------
// Packed f32x2 helpers (qproj fp32 GEMM)
// ---------------------------------------------------------------------------
__device__ __forceinline__ unsigned long long bcast2(float a) {
    unsigned long long r;
    unsigned int ai = __float_as_uint(a);
    asm("mov.b64 %0, {%1, %1};" : "=l"(r) : "r"(ai));
    return r;
}
__device__ __forceinline__ void fma2(unsigned long long& d,
                                     unsigned long long a,
                                     unsigned long long b) {
    asm("fma.rn.f32x2 %0, %1, %2, %0;" : "+l"(d) : "l"(a), "l"(b));
}

__device__ __forceinline__ uint32_t smem_u32(const void* p) {
    uint32_t a;
    asm("{ .reg .u64 t; cvta.to.shared.u64 t, %1; cvt.u32.u64 %0, t; }"
        : "=r"(a) : "l"(p));
    return a;
}

// mma.sync / ldmatrix / cp.async (baseline ISA, valid on plain sm_103 target)
__device__ __forceinline__ void ldm_x4(uint32_t* r, uint32_t addr) {
    asm volatile("ldmatrix.sync.aligned.m8n8.x4.shared.b16 {%0,%1,%2,%3}, [%4];"
        : "=r"(r[0]), "=r"(r[1]), "=r"(r[2]), "=r"(r[3]) : "r"(addr));
}
__device__ __forceinline__ void mma_bf16(float* c, const uint32_t* a,
                                         const uint32_t* b) {
    asm volatile(
        "mma.sync.aligned.m16n8k16.row.col.f32.bf16.bf16.f32 "
        "{%0,%1,%2,%3}, {%4,%5,%6,%7}, {%8,%9}, {%0,%1,%2,%3};"
        : "+f"(c[0]), "+f"(c[1]), "+f"(c[2]), "+f"(c[3])
        : "r"(a[0]), "r"(a[1]), "r"(a[2]), "r"(a[3]), "r"(b[0]), "r"(b[1]));
}
__device__ __forceinline__ void cp16(uint32_t dst, const void* src) {
    asm volatile("cp.async.cg.shared.global [%0], [%1], 16;"
        :: "r"(dst), "l"(src));
}
__device__ __forceinline__ void cp_commit() {
    asm volatile("cp.async.commit_group;");
}
template <int N>
__device__ __forceinline__ void cp_wait() {
    asm volatile("cp.async.wait_group %0;" :: "n"(N) : "memory");
}

// ---------------------------------------------------------------------------
// qproj: g_q = x @ q_w^T (4096x1024x1024), fp32, BM=BN=128, BK=16.
// Epilogue also emits bf16 copy into g_qbf (folds the old cvt<0> kernel).
// ---------------------------------------------------------------------------
#define BM 128
#define BN 128
#define BK 16

__global__ __launch_bounds__(256) void gemm_qproj_kernel(
    const float* __restrict__ A, const float* __restrict__ B, int M, int N, int K)
{
    float* __restrict__ C = (float*)g_q;
    __nv_bfloat16* __restrict__ Cbf = (__nv_bfloat16*)g_qbf;
    __shared__ __align__(16) float As[BK][BM];
    __shared__ __align__(16) float Bs[BK][BN];
    const int tid = threadIdx.x;
    const int tx = tid & 15;
    const int ty = tid >> 4;
    const int m0 = blockIdx.x * BM;
    const int n0 = blockIdx.y * BN;

    unsigned long long acc[8][4];
    #pragma unroll
    for (int i = 0; i < 8; i++)
        #pragma unroll
        for (int j = 0; j < 4; j++) acc[i][j] = 0ull;

    for (int kt = 0; kt < K; kt += BK) {
        #pragma unroll
        for (int p = 0; p < 2; p++) {
            int i = tid + p * 256;
            int row = i >> 2;
            int kq  = (i & 3) << 2;
            float4 av = *reinterpret_cast<const float4*>(
                &A[(size_t)(m0 + row) * K + kt + kq]);
            As[kq + 0][row] = av.x; As[kq + 1][row] = av.y;
            As[kq + 2][row] = av.z; As[kq + 3][row] = av.w;
            float4 bv = *reinterpret_cast<const float4*>(
                &B[(size_t)(n0 + row) * K + kt + kq]);
            Bs[kq + 0][row] = bv.x; Bs[kq + 1][row] = bv.y;
            Bs[kq + 2][row] = bv.z; Bs[kq + 3][row] = bv.w;
        }
        __syncthreads();
        #pragma unroll
        for (int k = 0; k < BK; k++) {
            float a[8];
            *reinterpret_cast<float4*>(&a[0]) =
                *reinterpret_cast<const float4*>(&As[k][ty * 4]);
            *reinterpret_cast<float4*>(&a[4]) =
                *reinterpret_cast<const float4*>(&As[k][ty * 4 + 64]);
            ulonglong2 b01 = *reinterpret_cast<const ulonglong2*>(&Bs[k][tx * 4]);
            ulonglong2 b23 = *reinterpret_cast<const ulonglong2*>(&Bs[k][tx * 4 + 64]);
            #pragma unroll
            for (int i = 0; i < 8; i++) {
                unsigned long long ab = bcast2(a[i]);
                fma2(acc[i][0], ab, b01.x);
                fma2(acc[i][1], ab, b01.y);
                fma2(acc[i][2], ab, b23.x);
                fma2(acc[i][3], ab, b23.y);
            }
        }
        __syncthreads();
    }

    #pragma unroll
    for (int i = 0; i < 8; i++) {
        int m = m0 + ty * 4 + (i < 4 ? i : 60 + i);
        float2 c0 = *reinterpret_cast<float2*>(&acc[i][0]);
        float2 c1 = *reinterpret_cast<float2*>(&acc[i][1]);
        float2 c2 = *reinterpret_cast<float2*>(&acc[i][2]);
        float2 c3 = *reinterpret_cast<float2*>(&acc[i][3]);
        *reinterpret_cast<float4*>(&C[(size_t)m * N + n0 + tx * 4]) =
            make_float4(c0.x, c0.y, c1.x, c1.y);
        *reinterpret_cast<float4*>(&C[(size_t)m * N + n0 + 64 + tx * 4]) =
            make_float4(c2.x, c2.y, c3.x, c3.y);
        // bf16 mirror (same values, rn-rounded)
        __nv_bfloat162 p0 = __floats2bfloat162_rn(c0.x, c0.y);
        __nv_bfloat162 p1 = __floats2bfloat162_rn(c1.x, c1.y);
        __nv_bfloat162 p2 = __floats2bfloat162_rn(c2.x, c2.y);
        __nv_bfloat162 p3 = __floats2bfloat162_rn(c3.x, c3.y);
        *reinterpret_cast<__nv_bfloat162*>(&Cbf[(size_t)m * N + n0 + tx * 4]) = p0;
        *reinterpret_cast<__nv_bfloat162*>(&Cbf[(size_t)m * N + n0 + tx * 4 + 2]) = p1;
        *reinterpret_cast<__nv_bfloat162*>(&Cbf[(size_t)m * N + n0 + 64 + tx * 4]) = p2;
        *reinterpret_cast<__nv_bfloat162*>(&Cbf[(size_t)m * N + n0 + 64 + tx * 4 + 2]) = p3;
    }
}

// ---------------------------------------------------------------------------
// keys fp32 -> bf16
// ---------------------------------------------------------------------------
__global__ __launch_bounds__(256) void cvt_keys_kernel(const float* __restrict__ src)
{
    __nv_bfloat16* __restrict__ dst = (__nv_bfloat16*)g_kbf;
    size_t i = (size_t)blockIdx.x * 256 + threadIdx.x;   // float4 index
    float4 v = reinterpret_cast<const float4*>(src)[i];
    __nv_bfloat162 p0 = __floats2bfloat162_rn(v.x, v.y);
    __nv_bfloat162 p1 = __floats2bfloat162_rn(v.z, v.w);
    __nv_bfloat162* dp = reinterpret_cast<__nv_bfloat162*>(dst) + 2 * i;
    dp[0] = p0; dp[1] = p1;
}

// ---------------------------------------------------------------------------
// approx scores = q_bf @ keys_bf^T via mma.sync (single bf16 term) -> bf16
// Tile 128x128, BK=32, 2-stage double buffer (40KB smem), 8 warps (64x32 each).
// Row stride 40 bf16 (80B): ldmatrix phase banks (r*20 mod 32) all distinct.
// Per barrier window: 12 ldmatrix + 32 mma per warp (2x the R8 window).
// ---------------------------------------------------------------------------
#define SROW2 40
#define STG_E (128 * SROW2)           // 5120 elems = 10240 B per array/stage
#define BKS 32

__global__ __launch_bounds__(256, 2) void scores_mma_kernel()
{
    __shared__ __align__(16) __nv_bfloat16 sA[2 * STG_E];   // 20 KB
    __shared__ __align__(16) __nv_bfloat16 sB[2 * STG_E];   // 20 KB

    const int tid = threadIdx.x;
    const int wid = tid >> 5;
    const int lid = tid & 31;
    const int m0 = blockIdx.x * 128;
    const int n0 = blockIdx.y * 128;

    const int base_m = (wid & 1) * 64;
    const int base_n = (wid >> 1) * 32;

    const uint32_t aA = smem_u32(sA), aB = smem_u32(sB);
    const uint32_t STB = STG_E * 2;   // 10240 bytes

    // cp.async: 512 16B-chunks per array per stage; thread t -> chunks t, t+256
    const int r0c = tid >> 2, c0c = tid & 3;              // chunk tid
    const int r1c = (tid + 256) >> 2, c1c = tid & 3;      // chunk tid+256
    const uint32_t dOff0 = r0c * 80 + c0c * 16;
    const uint32_t dOff1 = r1c * 80 + c1c * 16;
    const size_t gA0 = (size_t)(m0 + r0c) * DDIM + c0c * 8;
    const size_t gA1 = (size_t)(m0 + r1c) * DDIM + c1c * 8;
    const size_t gB0 = (size_t)(n0 + r0c) * DDIM + c0c * 8;
    const size_t gB1 = (size_t)(n0 + r1c) * DDIM + c1c * 8;

    // ldmatrix per-lane offsets (canonical x4 lane->row mapping)
    const uint32_t aOff = (uint32_t)(base_m + (lid & 7) + ((lid >> 3) & 1) * 8) * 80
                        + (uint32_t)(lid >> 4) * 16;
    const uint32_t bOff = (uint32_t)(base_n + (lid & 7) + ((lid >= 16) ? 8 : 0)) * 80
                        + (uint32_t)((lid >> 3) & 1) * 16;

    float c[4][4][4];
    #pragma unroll
    for (int i = 0; i < 4; i++)
        #pragma unroll
        for (int j = 0; j < 4; j++)
            #pragma unroll
            for (int k = 0; k < 4; k++) c[i][j][k] = 0.f;

    const int NKT = DDIM / BKS;  // 32

    // prologue: stage 0
    cp16(aA + dOff0, (const char*)g_qbf + gA0 * 2);
    cp16(aA + dOff1, (const char*)g_qbf + gA1 * 2);
    cp16(aB + dOff0, (const char*)g_kbf + gB0 * 2);
    cp16(aB + dOff1, (const char*)g_kbf + gB1 * 2);
    cp_commit();

    for (int kt = 0; kt < NKT; kt++) {
        if (kt + 1 < NKT) {
            const uint32_t so = ((kt + 1) & 1) * STB;
            const size_t ko = (size_t)(kt + 1) * BKS;
            cp16(aA + so + dOff0, (const char*)g_qbf + (gA0 + ko) * 2);
            cp16(aA + so + dOff1, (const char*)g_qbf + (gA1 + ko) * 2);
            cp16(aB + so + dOff0, (const char*)g_kbf + (gB0 + ko) * 2);
            cp16(aB + so + dOff1, (const char*)g_kbf + (gB1 + ko) * 2);
        }
        cp_commit();                  // constant group rate
        cp_wait<1>();                 // stage kt resident
        __syncthreads();

        const uint32_t so = (kt & 1) * STB;
        #pragma unroll
        for (int kk = 0; kk < 2; kk++) {          // two 16-k halves (k ascending)
            const uint32_t ko = kk * 32;          // 16 elems * 2B
            uint32_t ah[4][4], bh[2][4];
            #pragma unroll
            for (int mf = 0; mf < 4; mf++)
                ldm_x4(ah[mf], aA + so + aOff + ko + mf * (16 * 80));
            #pragma unroll
            for (int np = 0; np < 2; np++)
                ldm_x4(bh[np], aB + so + bOff + ko + np * (16 * 80));
            #pragma unroll
            for (int mf = 0; mf < 4; mf++)
                #pragma unroll
                for (int nf = 0; nf < 4; nf++)
                    mma_bf16(c[mf][nf], ah[mf], &bh[nf >> 1][(nf & 1) * 2]);
        }
        __syncthreads();
    }

    // epilogue: bf16 scores
    const int crow = lid >> 2;
    const int ccol = (lid & 3) * 2;
    #pragma unroll
    for (int mf = 0; mf < 4; mf++) {
        #pragma unroll
        for (int nf = 0; nf < 4; nf++) {
            int m = m0 + base_m + mf * 16 + crow;
            int n = n0 + base_n + nf * 8 + ccol;
            *reinterpret_cast<__nv_bfloat162*>(&g_sbf[(size_t)m * NKEY + n]) =
                __floats2bfloat162_rn(c[mf][nf][0], c[mf][nf][1]);
            *reinterpret_cast<__nv_bfloat162*>(&g_sbf[(size_t)(m + 8) * NKEY + n]) =
                __floats2bfloat162_rn(c[mf][nf][2], c[mf][nf][3]);
        }
    }
}

// ---------------------------------------------------------------------------
// Per-row: approx top-48 candidates -> BIT-EXACT R3-style fp32 rescore
// -> exact rank (JAX lowest-index tie-break) -> softmax -> weighted gather.
// ---------------------------------------------------------------------------
__global__ __launch_bounds__(128) void topk_out_kernel(
    const float* __restrict__ keys, const float* __restrict__ values,
    float* __restrict__ out)
{
    __shared__ float          sv[4096];
    __shared__ unsigned short si[4096];
    __shared__ __align__(16) float qrow[DDIM];
    __shared__ float rwv[4];
    __shared__ int   rws[4];
    __shared__ int   ci[NCAND];
    __shared__ float rs[NCAND];
    __shared__ int   sidx[KSEL];
    __shared__ float ssc[KSEL];
    __shared__ float sw[KSEL];
    __shared__ float sZ;

    const int tid = threadIdx.x;
    const int row = blockIdx.x;
    const __nv_bfloat16* srow = (const __nv_bfloat16*)g_sbf + (size_t)row * NKEY;

    #pragma unroll
    for (int j = tid; j < DDIM / 4; j += 128)
        reinterpret_cast<float4*>(qrow)[j] =
            reinterpret_cast<const float4*>((const float*)g_q + (size_t)row * DDIM)[j];

    float lv[KSEL];
    int   li[KSEL];
    #pragma unroll
    for (int j = 0; j < KSEL; j++) { lv[j] = -INFINITY; li[j] = 0; }

    for (int it = 0; it < NKEY / (128 * 8); it++) {
        int vec = it * 128 + tid;
        uint4 raw = reinterpret_cast<const uint4*>(srow)[vec];
        int base = vec * 8;
        uint32_t ws[4] = {raw.x, raw.y, raw.z, raw.w};
        #pragma unroll
        for (int h = 0; h < 4; h++) {
            #pragma unroll
            for (int e = 0; e < 2; e++) {
                float v = __uint_as_float(e == 0 ? (ws[h] << 16)
                                                 : (ws[h] & 0xffff0000u));
                int idx = base + h * 2 + e;
                if (v > lv[0]) {
                    #pragma unroll
                    for (int j = 0; j < KSEL; j++) {
                        float nxt  = (j < KSEL - 1) ? lv[j + 1] : INFINITY;
                        int   nxti = (j < KSEL - 1) ? li[j + 1] : 0;
                        if (nxt <= v)        { lv[j] = nxt; li[j] = nxti; }
                        else if (lv[j] <= v) { lv[j] = v;   li[j] = idx;  }
                    }
                }
            }
        }
    }

    #pragma unroll
    for (int j = 0; j < KSEL; j++) {
        sv[j * 128 + tid] = lv[j];
        si[j * 128 + tid] = (unsigned short)li[j];
    }
    __syncthreads();

    const int lane = tid & 31, warp = tid >> 5;
    for (int it = 0; it < NCAND; it++) {
        float best = -INFINITY; int bslot = 0;
        #pragma unroll 8
        for (int jj = tid; jj < 4096; jj += 128) {
            float v = sv[jj];
            if (v > best) { best = v; bslot = jj; }
        }
        #pragma unroll
        for (int o = 16; o > 0; o >>= 1) {
            float ov = __shfl_down_sync(0xffffffffu, best, o);
            int   os = __shfl_down_sync(0xffffffffu, bslot, o);
            if (ov > best) { best = ov; bslot = os; }
        }
        if (lane == 0) { rwv[warp] = best; rws[warp] = bslot; }
        __syncthreads();
        if (tid == 0) {
            float b = rwv[0]; int bs = rws[0];
            #pragma unroll
            for (int w = 1; w < 4; w++)
                if (rwv[w] > b) { b = rwv[w]; bs = rws[w]; }
            ci[it] = (int)si[bs];
            sv[bs] = -INFINITY;
        }
        __syncthreads();
    }

    // BIT-EXACT rescore: one thread per candidate, sequential rn-fma chain.
    if (tid < NCAND) {
        const float* krow = keys + (size_t)ci[tid] * DDIM;
        float acc = 0.f;
        #pragma unroll 8
        for (int k = 0; k < DDIM; k++)
            acc = __fmaf_rn(qrow[k], __ldg(&krow[k]), acc);
        rs[tid] = acc;
    }
    __syncthreads();

    if (tid < NCAND) {
        float sc = rs[tid];
        int   myi = ci[tid];
        int rank = 0;
        #pragma unroll
        for (int j = 0; j < NCAND; j++) {
            float sj = rs[j];
            rank += (sj > sc) || (sj == sc && ci[j] < myi);
        }
        if (rank < KSEL) { sidx[rank] = myi; ssc[rank] = sc; }
    }
    __syncthreads();

    if (tid < KSEL) sw[tid] = expf(ssc[tid] - ssc[0]);
    __syncthreads();
    if (tid == 0) {
        float z = 0.f;
        #pragma unroll
        for (int j = 0; j < KSEL; j++) z += sw[j];
        sZ = z;
    }
    __syncthreads();
    const float invZ = 1.0f / sZ;

    for (int d = tid; d < DDIM; d += 128) {
        float acc = 0.f;
        #pragma unroll 8
        for (int k = 0; k < KSEL; k++)
            acc += sw[k] * values[(size_t)sidx[k] * DDIM + d];
        out[(size_t)row * DDIM + d] = acc * invZ;
    }
}

// ---------------------------------------------------------------------------
extern "C" void kernel_launch(void* const* d_in, const int* in_sizes, int n_in,
                              void* d_out, int out_size) {
    const float* x      = (const float*)d_in[0];
    const float* q_w    = (const float*)d_in[1];
    const float* keys   = (const float*)d_in[2];
    const float* values = (const float*)d_in[3];
    float* out = (float*)d_out;

    cudaStream_t st = cudaStreamPerThread;

    // 1) q = x @ q_w^T -> g_q (fp32) + g_qbf (bf16 mirror)
    dim3 g1(NROWS / BM, DDIM / BN);
    gemm_qproj_kernel<<<g1, 256, 0, st>>>(x, q_w, NROWS, DDIM, DDIM);

    // 2) keys -> bf16
    cvt_keys_kernel<<<(int)(((size_t)NKEY * DDIM / 4) / 256), 256, 0, st>>>(keys);

    // 3) approx scores via bf16 mma -> g_sbf (m fastest for L2 keys reuse)
    dim3 g2(NROWS / 128, NKEY / 128);
    scores_mma_kernel<<<g2, 256, 0, st>>>();

    // 4) candidates + bit-exact rescore + softmax + gather
    topk_out_kernel<<<NROWS, 128, 0, st>>>(keys, values, out);
}

// round 10
// speedup vs baseline: 4.0551x; 1.3664x over previous
#include <cuda_runtime.h>
#include <cuda_bf16.h>
#include <cstdint>

#define NROWS 4096
#define DDIM  1024
#define NKEY  65536
#define KSEL  32
#define NCAND 48
#define CAP   3072

// ---------------------------------------------------------------------------
// Static device scratch (allocation-guard safe). NEVER passed as host-side
// kernel args (host shadow trap!) — referenced from device code only.
// ---------------------------------------------------------------------------
__device__ float g_q[(size_t)NROWS * DDIM];                 // 16 MB (fp32 q)
__device__ __nv_bfloat16 g_qbf[(size_t)NROWS * DDIM];       // 8 MB
__device__ __nv_bfloat16 g_kbf[(size_t)NKEY * DDIM];        // 128 MB
__device__ __nv_bfloat16 g_sbf[(size_t)NROWS * NKEY];       // 512 MB (bf16 scores)

// ---------------------------------------------------------------------------
// Packed f32x2 helpers (qproj fp32 GEMM)
// ---------------------------------------------------------------------------
__device__ __forceinline__ unsigned long long bcast2(float a) {
    unsigned long long r;
    unsigned int ai = __float_as_uint(a);
    asm("mov.b64 %0, {%1, %1};" : "=l"(r) : "r"(ai));
    return r;
}
__device__ __forceinline__ void fma2(unsigned long long& d,
                                     unsigned long long a,
                                     unsigned long long b) {
    asm("fma.rn.f32x2 %0, %1, %2, %0;" : "+l"(d) : "l"(a), "l"(b));
}

__device__ __forceinline__ uint32_t smem_u32(const void* p) {
    uint32_t a;
    asm("{ .reg .u64 t; cvta.to.shared.u64 t, %1; cvt.u32.u64 %0, t; }"
        : "=r"(a) : "l"(p));
    return a;
}

// mma.sync / ldmatrix / cp.async (baseline ISA, valid on plain sm_103 target)
__device__ __forceinline__ void ldm_x4(uint32_t* r, uint32_t addr) {
    asm volatile("ldmatrix.sync.aligned.m8n8.x4.shared.b16 {%0,%1,%2,%3}, [%4];"
        : "=r"(r[0]), "=r"(r[1]), "=r"(r[2]), "=r"(r[3]) : "r"(addr));
}
__device__ __forceinline__ void mma_bf16(float* c, const uint32_t* a,
                                         const uint32_t* b) {
    asm volatile(
        "mma.sync.aligned.m16n8k16.row.col.f32.bf16.bf16.f32 "
        "{%0,%1,%2,%3}, {%4,%5,%6,%7}, {%8,%9}, {%0,%1,%2,%3};"
        : "+f"(c[0]), "+f"(c[1]), "+f"(c[2]), "+f"(c[3])
        : "r"(a[0]), "r"(a[1]), "r"(a[2]), "r"(a[3]), "r"(b[0]), "r"(b[1]));
}
__device__ __forceinline__ void cp16(uint32_t dst, const void* src) {
    asm volatile("cp.async.cg.shared.global [%0], [%1], 16;"
        :: "r"(dst), "l"(src));
}
__device__ __forceinline__ void cp_commit() {
    asm volatile("cp.async.commit_group;");
}
template <int N>
__device__ __forceinline__ void cp_wait() {
    asm volatile("cp.async.wait_group %0;" :: "n"(N) : "memory");
}
__device__ __forceinline__ uint32_t bmax2(uint32_t a, uint32_t b) {
    uint32_t d;
    asm("max.bf16x2 %0, %1, %2;" : "=r"(d) : "r"(a), "r"(b));
    return d;
}

// ---------------------------------------------------------------------------
// qproj: g_q = x @ q_w^T (4096x1024x1024), fp32, BM=BN=128, BK=16.
// Epilogue also emits bf16 copy into g_qbf.
// ---------------------------------------------------------------------------
#define BM 128
#define BN 128
#define BK 16

__global__ __launch_bounds__(256) void gemm_qproj_kernel(
    const float* __restrict__ A, const float* __restrict__ B, int M, int N, int K)
{
    float* __restrict__ C = (float*)g_q;
    __nv_bfloat16* __restrict__ Cbf = (__nv_bfloat16*)g_qbf;
    __shared__ __align__(16) float As[BK][BM];
    __shared__ __align__(16) float Bs[BK][BN];
    const int tid = threadIdx.x;
    const int tx = tid & 15;
    const int ty = tid >> 4;
    const int m0 = blockIdx.x * BM;
    const int n0 = blockIdx.y * BN;

    unsigned long long acc[8][4];
    #pragma unroll
    for (int i = 0; i < 8; i++)
        #pragma unroll
        for (int j = 0; j < 4; j++) acc[i][j] = 0ull;

    for (int kt = 0; kt < K; kt += BK) {
        #pragma unroll
        for (int p = 0; p < 2; p++) {
            int i = tid + p * 256;
            int row = i >> 2;
            int kq  = (i & 3) << 2;
            float4 av = *reinterpret_cast<const float4*>(
                &A[(size_t)(m0 + row) * K + kt + kq]);
            As[kq + 0][row] = av.x; As[kq + 1][row] = av.y;
            As[kq + 2][row] = av.z; As[kq + 3][row] = av.w;
            float4 bv = *reinterpret_cast<const float4*>(
                &B[(size_t)(n0 + row) * K + kt + kq]);
            Bs[kq + 0][row] = bv.x; Bs[kq + 1][row] = bv.y;
            Bs[kq + 2][row] = bv.z; Bs[kq + 3][row] = bv.w;
        }
        __syncthreads();
        #pragma unroll
        for (int k = 0; k < BK; k++) {
            float a[8];
            *reinterpret_cast<float4*>(&a[0]) =
                *reinterpret_cast<const float4*>(&As[k][ty * 4]);
            *reinterpret_cast<float4*>(&a[4]) =
                *reinterpret_cast<const float4*>(&As[k][ty * 4 + 64]);
            ulonglong2 b01 = *reinterpret_cast<const ulonglong2*>(&Bs[k][tx * 4]);
            ulonglong2 b23 = *reinterpret_cast<const ulonglong2*>(&Bs[k][tx * 4 + 64]);
            #pragma unroll
            for (int i = 0; i < 8; i++) {
                unsigned long long ab = bcast2(a[i]);
                fma2(acc[i][0], ab, b01.x);
                fma2(acc[i][1], ab, b01.y);
                fma2(acc[i][2], ab, b23.x);
                fma2(acc[i][3], ab, b23.y);
            }
        }
        __syncthreads();
    }

    #pragma unroll
    for (int i = 0; i < 8; i++) {
        int m = m0 + ty * 4 + (i < 4 ? i : 60 + i);
        float2 c0 = *reinterpret_cast<float2*>(&acc[i][0]);
        float2 c1 = *reinterpret_cast<float2*>(&acc[i][1]);
        float2 c2 = *reinterpret_cast<float2*>(&acc[i][2]);
        float2 c3 = *reinterpret_cast<float2*>(&acc[i][3]);
        *reinterpret_cast<float4*>(&C[(size_t)m * N + n0 + tx * 4]) =
            make_float4(c0.x, c0.y, c1.x, c1.y);
        *reinterpret_cast<float4*>(&C[(size_t)m * N + n0 + 64 + tx * 4]) =
            make_float4(c2.x, c2.y, c3.x, c3.y);
        __nv_bfloat162 p0 = __floats2bfloat162_rn(c0.x, c0.y);
        __nv_bfloat162 p1 = __floats2bfloat162_rn(c1.x, c1.y);
        __nv_bfloat162 p2 = __floats2bfloat162_rn(c2.x, c2.y);
        __nv_bfloat162 p3 = __floats2bfloat162_rn(c3.x, c3.y);
        *reinterpret_cast<__nv_bfloat162*>(&Cbf[(size_t)m * N + n0 + tx * 4]) = p0;
        *reinterpret_cast<__nv_bfloat162*>(&Cbf[(size_t)m * N + n0 + tx * 4 + 2]) = p1;
        *reinterpret_cast<__nv_bfloat162*>(&Cbf[(size_t)m * N + n0 + 64 + tx * 4]) = p2;
        *reinterpret_cast<__nv_bfloat162*>(&Cbf[(size_t)m * N + n0 + 64 + tx * 4 + 2]) = p3;
    }
}

// ---------------------------------------------------------------------------
// keys fp32 -> bf16
// ---------------------------------------------------------------------------
__global__ __launch_bounds__(256) void cvt_keys_kernel(const float* __restrict__ src)
{
    __nv_bfloat16* __restrict__ dst = (__nv_bfloat16*)g_kbf;
    size_t i = (size_t)blockIdx.x * 256 + threadIdx.x;   // float4 index
    float4 v = reinterpret_cast<const float4*>(src)[i];
    __nv_bfloat162 p0 = __floats2bfloat162_rn(v.x, v.y);
    __nv_bfloat162 p1 = __floats2bfloat162_rn(v.z, v.w);
    __nv_bfloat162* dp = reinterpret_cast<__nv_bfloat162*>(dst) + 2 * i;
    dp[0] = p0; dp[1] = p1;
}

// ---------------------------------------------------------------------------
// approx scores = q_bf @ keys_bf^T via mma.sync (single bf16 term) -> bf16
// Tile 128x128, BK=32, 2-stage double buffer (40KB smem), 8 warps (64x32 each).
// (unchanged from R9 — bit-identical scores)
// ---------------------------------------------------------------------------
#define SROW2 40
#define STG_E (128 * SROW2)
#define BKS 32

__global__ __launch_bounds__(256, 2) void scores_mma_kernel()
{
    __shared__ __align__(16) __nv_bfloat16 sA[2 * STG_E];
    __shared__ __align__(16) __nv_bfloat16 sB[2 * STG_E];

    const int tid = threadIdx.x;
    const int wid = tid >> 5;
    const int lid = tid & 31;
    const int m0 = blockIdx.x * 128;
    const int n0 = blockIdx.y * 128;

    const int base_m = (wid & 1) * 64;
    const int base_n = (wid >> 1) * 32;

    const uint32_t aA = smem_u32(sA), aB = smem_u32(sB);
    const uint32_t STB = STG_E * 2;

    const int r0c = tid >> 2, c0c = tid & 3;
    const int r1c = (tid + 256) >> 2, c1c = tid & 3;
    const uint32_t dOff0 = r0c * 80 + c0c * 16;
    const uint32_t dOff1 = r1c * 80 + c1c * 16;
    const size_t gA0 = (size_t)(m0 + r0c) * DDIM + c0c * 8;
    const size_t gA1 = (size_t)(m0 + r1c) * DDIM + c1c * 8;
    const size_t gB0 = (size_t)(n0 + r0c) * DDIM + c0c * 8;
    const size_t gB1 = (size_t)(n0 + r1c) * DDIM + c1c * 8;

    const uint32_t aOff = (uint32_t)(base_m + (lid & 7) + ((lid >> 3) & 1) * 8) * 80
                        + (uint32_t)(lid >> 4) * 16;
    const uint32_t bOff = (uint32_t)(base_n + (lid & 7) + ((lid >= 16) ? 8 : 0)) * 80
                        + (uint32_t)((lid >> 3) & 1) * 16;

    float c[4][4][4];
    #pragma unroll
    for (int i = 0; i < 4; i++)
        #pragma unroll
        for (int j = 0; j < 4; j++)
            #pragma unroll
            for (int k = 0; k < 4; k++) c[i][j][k] = 0.f;

    const int NKT = DDIM / BKS;  // 32

    cp16(aA + dOff0, (const char*)g_qbf + gA0 * 2);
    cp16(aA + dOff1, (const char*)g_qbf + gA1 * 2);
    cp16(aB + dOff0, (const char*)g_kbf + gB0 * 2);
    cp16(aB + dOff1, (const char*)g_kbf + gB1 * 2);
    cp_commit();

    for (int kt = 0; kt < NKT; kt++) {
        if (kt + 1 < NKT) {
            const uint32_t so = ((kt + 1) & 1) * STB;
            const size_t ko = (size_t)(kt + 1) * BKS;
            cp16(aA + so + dOff0, (const char*)g_qbf + (gA0 + ko) * 2);
            cp16(aA + so + dOff1, (const char*)g_qbf + (gA1 + ko) * 2);
            cp16(aB + so + dOff0, (const char*)g_kbf + (gB0 + ko) * 2);
            cp16(aB + so + dOff1, (const char*)g_kbf + (gB1 + ko) * 2);
        }
        cp_commit();
        cp_wait<1>();
        __syncthreads();

        const uint32_t so = (kt & 1) * STB;
        #pragma unroll
        for (int kk = 0; kk < 2; kk++) {
            const uint32_t ko = kk * 32;
            uint32_t ah[4][4], bh[2][4];
            #pragma unroll
            for (int mf = 0; mf < 4; mf++)
                ldm_x4(ah[mf], aA + so + aOff + ko + mf * (16 * 80));
            #pragma unroll
            for (int np = 0; np < 2; np++)
                ldm_x4(bh[np], aB + so + bOff + ko + np * (16 * 80));
            #pragma unroll
            for (int mf = 0; mf < 4; mf++)
                #pragma unroll
                for (int nf = 0; nf < 4; nf++)
                    mma_bf16(c[mf][nf], ah[mf], &bh[nf >> 1][(nf & 1) * 2]);
        }
        __syncthreads();
    }

    const int crow = lid >> 2;
    const int ccol = (lid & 3) * 2;
    #pragma unroll
    for (int mf = 0; mf < 4; mf++) {
        #pragma unroll
        for (int nf = 0; nf < 4; nf++) {
            int m = m0 + base_m + mf * 16 + crow;
            int n = n0 + base_n + nf * 8 + ccol;
            *reinterpret_cast<__nv_bfloat162*>(&g_sbf[(size_t)m * NKEY + n]) =
                __floats2bfloat162_rn(c[mf][nf][0], c[mf][nf][1]);
            *reinterpret_cast<__nv_bfloat162*>(&g_sbf[(size_t)(m + 8) * NKEY + n]) =
                __floats2bfloat162_rn(c[mf][nf][2], c[mf][nf][3]);
        }
    }
}

// ---------------------------------------------------------------------------
// Per-row topk: sample -> threshold tau (16th of 2048 samples) -> filtered
// scan (max.bf16x2 coarse test, ~1 op/elem) -> buffer -> top-48 by argmax
// -> BIT-EXACT sequential-fma rescore -> rank -> softmax -> gather.
// ---------------------------------------------------------------------------
__global__ __launch_bounds__(128) void topk_out_kernel(
    const float* __restrict__ keys, const float* __restrict__ values,
    float* __restrict__ out)
{
    __shared__ float cbufV[CAP];          // also holds 2048 samples in phase 1
    __shared__ int   cbufI[CAP];
    __shared__ __align__(16) float qrow[DDIM];
    __shared__ float rwv[4];
    __shared__ int   rws[4];
    __shared__ float gwv;
    __shared__ int   gws;
    __shared__ int   scnt;
    __shared__ int   ci[NCAND];
    __shared__ float rs[NCAND];
    __shared__ int   sidx[KSEL];
    __shared__ float ssc[KSEL];
    __shared__ float sw[KSEL];
    __shared__ float sZ;

    const int tid = threadIdx.x;
    const int lane = tid & 31, warp = tid >> 5;
    const int row = blockIdx.x;
    const __nv_bfloat16* srow = (const __nv_bfloat16*)g_sbf + (size_t)row * NKEY;

    // q row (fp32) for rescoring
    #pragma unroll
    for (int j = tid; j < DDIM / 4; j += 128)
        reinterpret_cast<float4*>(qrow)[j] =
            reinterpret_cast<const float4*>((const float*)g_q + (size_t)row * DDIM)[j];

    // ---- phase 1: sample every 32nd score (2048 samples) into cbufV
    #pragma unroll
    for (int j = 0; j < 16; j++) {
        int s = (j * 128 + tid) * 32;
        uint32_t raw = (uint32_t)*reinterpret_cast<const unsigned short*>(&srow[s]);
        cbufV[j * 128 + tid] = __uint_as_float(raw << 16);
    }
    __syncthreads();

    // tau = 16th largest sample (16 block-argmax rounds with invalidation)
    float thr = 0.f;
    for (int it = 0; it < 16; it++) {
        float best = -INFINITY; int bslot = 0;
        #pragma unroll
        for (int jj = tid; jj < 2048; jj += 128) {
            float v = cbufV[jj];
            if (v > best) { best = v; bslot = jj; }
        }
        #pragma unroll
        for (int o = 16; o > 0; o >>= 1) {
            float ov = __shfl_down_sync(0xffffffffu, best, o);
            int   os = __shfl_down_sync(0xffffffffu, bslot, o);
            if (ov > best) { best = ov; bslot = os; }
        }
        if (lane == 0) { rwv[warp] = best; rws[warp] = bslot; }
        __syncthreads();
        if (tid == 0) {
            float b = rwv[0]; int bs = rws[0];
            #pragma unroll
            for (int w = 1; w < 4; w++)
                if (rwv[w] > b) { b = rwv[w]; bs = rws[w]; }
            gwv = b;
            cbufV[bs] = -INFINITY;
        }
        __syncthreads();
        thr = gwv;
    }
    if (tid == 0) scnt = 0;
    __syncthreads();

    // ---- phase 2: filtered scan, append (val, idx) >= thr to buffer
    for (int it = 0; it < NKEY / (128 * 8); it++) {
        int vec = it * 128 + tid;
        uint4 raw = reinterpret_cast<const uint4*>(srow)[vec];
        uint32_t m01 = bmax2(raw.x, raw.y);
        uint32_t m23 = bmax2(raw.z, raw.w);
        uint32_t mm  = bmax2(m01, m23);
        float flo = __uint_as_float(mm << 16);
        float fhi = __uint_as_float(mm & 0xffff0000u);
        if (flo >= thr || fhi >= thr) {
            int base = vec * 8;
            uint32_t ws[4] = {raw.x, raw.y, raw.z, raw.w};
            #pragma unroll
            for (int h = 0; h < 4; h++) {
                #pragma unroll
                for (int e = 0; e < 2; e++) {
                    float v = __uint_as_float(e == 0 ? (ws[h] << 16)
                                                     : (ws[h] & 0xffff0000u));
                    if (v >= thr) {
                        int pos = atomicAdd(&scnt, 1);
                        if (pos < CAP) { cbufV[pos] = v; cbufI[pos] = base + h * 2 + e; }
                    }
                }
            }
        }
    }
    __syncthreads();
    const int m = min(scnt, CAP);

    // ---- phase 3: top-48 candidates by block argmax over buffer
    for (int it = 0; it < NCAND; it++) {
        float best = -INFINITY; int bslot = -1;
        for (int jj = tid; jj < m; jj += 128) {
            float v = cbufV[jj];
            if (v > best) { best = v; bslot = jj; }
        }
        #pragma unroll
        for (int o = 16; o > 0; o >>= 1) {
            float ov = __shfl_down_sync(0xffffffffu, best, o);
            int   os = __shfl_down_sync(0xffffffffu, bslot, o);
            if (ov > best) { best = ov; bslot = os; }
        }
        if (lane == 0) { rwv[warp] = best; rws[warp] = bslot; }
        __syncthreads();
        if (tid == 0) {
            float b = rwv[0]; int bs = rws[0];
            #pragma unroll
            for (int w = 1; w < 4; w++)
                if (rwv[w] > b) { b = rwv[w]; bs = rws[w]; }
            if (bs >= 0) { ci[it] = cbufI[bs]; cbufV[bs] = -INFINITY; }
            else         { ci[it] = -(it + 1); }   // sentinel (m < 48)
        }
        __syncthreads();
    }

    // ---- phase 4: BIT-EXACT rescore (sequential rn-fma chain, k ascending)
    if (tid < NCAND) {
        int cidx = ci[tid];
        if (cidx >= 0) {
            const float* krow = keys + (size_t)cidx * DDIM;
            float acc = 0.f;
            #pragma unroll 8
            for (int k = 0; k < DDIM; k++)
                acc = __fmaf_rn(qrow[k], __ldg(&krow[k]), acc);
            rs[tid] = acc;
        } else {
            rs[tid] = -INFINITY;
        }
    }
    __syncthreads();

    // exact rank with stable (lower-index-first) tie-break; select top-32
    if (tid < NCAND) {
        float sc = rs[tid];
        int   myi = ci[tid];
        int rank = 0;
        #pragma unroll
        for (int j = 0; j < NCAND; j++) {
            float sj = rs[j];
            rank += (sj > sc) || (sj == sc && ci[j] < myi);
        }
        if (rank < KSEL) { sidx[rank] = myi; ssc[rank] = sc; }
    }
    __syncthreads();

    // softmax over exact top-32 (TEMP=1); ssc[0] is the max
    if (tid < KSEL) sw[tid] = expf(ssc[tid] - ssc[0]);
    __syncthreads();
    if (tid == 0) {
        float z = 0.f;
        #pragma unroll
        for (int j = 0; j < KSEL; j++) z += sw[j];
        sZ = z;
    }
    __syncthreads();
    const float invZ = 1.0f / sZ;

    // weighted gather of values rows (GATING=1)
    for (int d = tid; d < DDIM; d += 128) {
        float acc = 0.f;
        #pragma unroll 8
        for (int k = 0; k < KSEL; k++)
            acc += sw[k] * values[(size_t)sidx[k] * DDIM + d];
        out[(size_t)row * DDIM + d] = acc * invZ;
    }
}

// ---------------------------------------------------------------------------
extern "C" void kernel_launch(void* const* d_in, const int* in_sizes, int n_in,
                              void* d_out, int out_size) {
    const float* x      = (const float*)d_in[0];
    const float* q_w    = (const float*)d_in[1];
    const float* keys   = (const float*)d_in[2];
    const float* values = (const float*)d_in[3];
    float* out = (float*)d_out;

    cudaStream_t st = cudaStreamPerThread;

    // 1) q = x @ q_w^T -> g_q (fp32) + g_qbf (bf16 mirror)
    dim3 g1(NROWS / BM, DDIM / BN);
    gemm_qproj_kernel<<<g1, 256, 0, st>>>(x, q_w, NROWS, DDIM, DDIM);

    // 2) keys -> bf16
    cvt_keys_kernel<<<(int)(((size_t)NKEY * DDIM / 4) / 256), 256, 0, st>>>(keys);

    // 3) approx scores via bf16 mma -> g_sbf
    dim3 g2(NROWS / 128, NKEY / 128);
    scores_mma_kernel<<<g2, 256, 0, st>>>();

    // 4) threshold-filtered candidates + bit-exact rescore + softmax + gather
    topk_out_kernel<<<NROWS, 128, 0, st>>>(keys, values, out);
}

// round 11
// speedup vs baseline: 4.3042x; 1.0614x over previous
#include <cuda_runtime.h>
#include <cuda_bf16.h>
#include <cstdint>

#define NROWS 4096
#define DDIM  1024
#define NKEY  65536
#define KSEL  32
#define NCAND 48
#define NBLK  512          // NKEY / 128 score blocks per row
#define CAP2  2048

// ---------------------------------------------------------------------------
// Static device scratch (allocation-guard safe). NEVER passed as host-side
// kernel args (host shadow trap!) — referenced from device code only.
// ---------------------------------------------------------------------------
__device__ float g_q[(size_t)NROWS * DDIM];                 // 16 MB (fp32 q)
__device__ __nv_bfloat16 g_qbf[(size_t)NROWS * DDIM];       // 8 MB
__device__ __nv_bfloat16 g_kbf[(size_t)NKEY * DDIM];        // 128 MB
__device__ __nv_bfloat16 g_sbf[(size_t)NROWS * NKEY];       // 512 MB (bf16 scores)
__device__ unsigned short g_bmax[(size_t)NROWS * NBLK];     // 4 MB (per-block max)

// ---------------------------------------------------------------------------
// Packed f32x2 helpers (qproj fp32 GEMM)
// ---------------------------------------------------------------------------
__device__ __forceinline__ unsigned long long bcast2(float a) {
    unsigned long long r;
    unsigned int ai = __float_as_uint(a);
    asm("mov.b64 %0, {%1, %1};" : "=l"(r) : "r"(ai));
    return r;
}
__device__ __forceinline__ void fma2(unsigned long long& d,
                                     unsigned long long a,
                                     unsigned long long b) {
    asm("fma.rn.f32x2 %0, %1, %2, %0;" : "+l"(d) : "l"(a), "l"(b));
}

__device__ __forceinline__ uint32_t smem_u32(const void* p) {
    uint32_t a;
    asm("{ .reg .u64 t; cvta.to.shared.u64 t, %1; cvt.u32.u64 %0, t; }"
        : "=r"(a) : "l"(p));
    return a;
}

// mma.sync / ldmatrix / cp.async (baseline ISA, valid on plain sm_103 target)
__device__ __forceinline__ void ldm_x4(uint32_t* r, uint32_t addr) {
    asm volatile("ldmatrix.sync.aligned.m8n8.x4.shared.b16 {%0,%1,%2,%3}, [%4];"
        : "=r"(r[0]), "=r"(r[1]), "=r"(r[2]), "=r"(r[3]) : "r"(addr));
}
__device__ __forceinline__ void mma_bf16(float* c, const uint32_t* a,
                                         const uint32_t* b) {
    asm volatile(
        "mma.sync.aligned.m16n8k16.row.col.f32.bf16.bf16.f32 "
        "{%0,%1,%2,%3}, {%4,%5,%6,%7}, {%8,%9}, {%0,%1,%2,%3};"
        : "+f"(c[0]), "+f"(c[1]), "+f"(c[2]), "+f"(c[3])
        : "r"(a[0]), "r"(a[1]), "r"(a[2]), "r"(a[3]), "r"(b[0]), "r"(b[1]));
}
__device__ __forceinline__ void cp16(uint32_t dst, const void* src) {
    asm volatile("cp.async.cg.shared.global [%0], [%1], 16;"
        :: "r"(dst), "l"(src));
}
__device__ __forceinline__ void cp_commit() {
    asm volatile("cp.async.commit_group;");
}
template <int N>
__device__ __forceinline__ void cp_wait() {
    asm volatile("cp.async.wait_group %0;" :: "n"(N) : "memory");
}

// ---------------------------------------------------------------------------
// qproj: g_q = x @ q_w^T (4096x1024x1024), fp32, BM=BN=128, BK=16.
// Epilogue also emits bf16 copy into g_qbf.
// ---------------------------------------------------------------------------
#define BM 128
#define BN 128
#define BK 16

__global__ __launch_bounds__(256) void gemm_qproj_kernel(
    const float* __restrict__ A, const float* __restrict__ B, int M, int N, int K)
{
    float* __restrict__ C = (float*)g_q;
    __nv_bfloat16* __restrict__ Cbf = (__nv_bfloat16*)g_qbf;
    __shared__ __align__(16) float As[BK][BM];
    __shared__ __align__(16) float Bs[BK][BN];
    const int tid = threadIdx.x;
    const int tx = tid & 15;
    const int ty = tid >> 4;
    const int m0 = blockIdx.x * BM;
    const int n0 = blockIdx.y * BN;

    unsigned long long acc[8][4];
    #pragma unroll
    for (int i = 0; i < 8; i++)
        #pragma unroll
        for (int j = 0; j < 4; j++) acc[i][j] = 0ull;

    for (int kt = 0; kt < K; kt += BK) {
        #pragma unroll
        for (int p = 0; p < 2; p++) {
            int i = tid + p * 256;
            int row = i >> 2;
            int kq  = (i & 3) << 2;
            float4 av = *reinterpret_cast<const float4*>(
                &A[(size_t)(m0 + row) * K + kt + kq]);
            As[kq + 0][row] = av.x; As[kq + 1][row] = av.y;
            As[kq + 2][row] = av.z; As[kq + 3][row] = av.w;
            float4 bv = *reinterpret_cast<const float4*>(
                &B[(size_t)(n0 + row) * K + kt + kq]);
            Bs[kq + 0][row] = bv.x; Bs[kq + 1][row] = bv.y;
            Bs[kq + 2][row] = bv.z; Bs[kq + 3][row] = bv.w;
        }
        __syncthreads();
        #pragma unroll
        for (int k = 0; k < BK; k++) {
            float a[8];
            *reinterpret_cast<float4*>(&a[0]) =
                *reinterpret_cast<const float4*>(&As[k][ty * 4]);
            *reinterpret_cast<float4*>(&a[4]) =
                *reinterpret_cast<const float4*>(&As[k][ty * 4 + 64]);
            ulonglong2 b01 = *reinterpret_cast<const ulonglong2*>(&Bs[k][tx * 4]);
            ulonglong2 b23 = *reinterpret_cast<const ulonglong2*>(&Bs[k][tx * 4 + 64]);
            #pragma unroll
            for (int i = 0; i < 8; i++) {
                unsigned long long ab = bcast2(a[i]);
                fma2(acc[i][0], ab, b01.x);
                fma2(acc[i][1], ab, b01.y);
                fma2(acc[i][2], ab, b23.x);
                fma2(acc[i][3], ab, b23.y);
            }
        }
        __syncthreads();
    }

    #pragma unroll
    for (int i = 0; i < 8; i++) {
        int m = m0 + ty * 4 + (i < 4 ? i : 60 + i);
        float2 c0 = *reinterpret_cast<float2*>(&acc[i][0]);
        float2 c1 = *reinterpret_cast<float2*>(&acc[i][1]);
        float2 c2 = *reinterpret_cast<float2*>(&acc[i][2]);
        float2 c3 = *reinterpret_cast<float2*>(&acc[i][3]);
        *reinterpret_cast<float4*>(&C[(size_t)m * N + n0 + tx * 4]) =
            make_float4(c0.x, c0.y, c1.x, c1.y);
        *reinterpret_cast<float4*>(&C[(size_t)m * N + n0 + 64 + tx * 4]) =
            make_float4(c2.x, c2.y, c3.x, c3.y);
        __nv_bfloat162 p0 = __floats2bfloat162_rn(c0.x, c0.y);
        __nv_bfloat162 p1 = __floats2bfloat162_rn(c1.x, c1.y);
        __nv_bfloat162 p2 = __floats2bfloat162_rn(c2.x, c2.y);
        __nv_bfloat162 p3 = __floats2bfloat162_rn(c3.x, c3.y);
        *reinterpret_cast<__nv_bfloat162*>(&Cbf[(size_t)m * N + n0 + tx * 4]) = p0;
        *reinterpret_cast<__nv_bfloat162*>(&Cbf[(size_t)m * N + n0 + tx * 4 + 2]) = p1;
        *reinterpret_cast<__nv_bfloat162*>(&Cbf[(size_t)m * N + n0 + 64 + tx * 4]) = p2;
        *reinterpret_cast<__nv_bfloat162*>(&Cbf[(size_t)m * N + n0 + 64 + tx * 4 + 2]) = p3;
    }
}

// ---------------------------------------------------------------------------
// keys fp32 -> bf16
// ---------------------------------------------------------------------------
__global__ __launch_bounds__(256) void cvt_keys_kernel(const float* __restrict__ src)
{
    __nv_bfloat16* __restrict__ dst = (__nv_bfloat16*)g_kbf;
    size_t i = (size_t)blockIdx.x * 256 + threadIdx.x;   // float4 index
    float4 v = reinterpret_cast<const float4*>(src)[i];
    __nv_bfloat162 p0 = __floats2bfloat162_rn(v.x, v.y);
    __nv_bfloat162 p1 = __floats2bfloat162_rn(v.z, v.w);
    __nv_bfloat162* dp = reinterpret_cast<__nv_bfloat162*>(dst) + 2 * i;
    dp[0] = p0; dp[1] = p1;
}

// ---------------------------------------------------------------------------
// approx scores = q_bf @ keys_bf^T via mma.sync (single bf16 term) -> bf16
// Tile 128x128, BK=32, 2-stage double buffer, 8 warps (64x32 each).
// Epilogue ALSO writes per-(row, 128-col block) max into g_bmax (bf16 bits);
// rn() is monotonic so rn(max v) == max(rn(v)) == max of stored scores.
// ---------------------------------------------------------------------------
#define SROW2 40
#define STG_E (128 * SROW2)
#define BKS 32

__global__ __launch_bounds__(256, 2) void scores_mma_kernel()
{
    __shared__ __align__(16) __nv_bfloat16 sA[2 * STG_E];
    __shared__ __align__(16) __nv_bfloat16 sB[2 * STG_E];

    const int tid = threadIdx.x;
    const int wid = tid >> 5;
    const int lid = tid & 31;
    const int m0 = blockIdx.x * 128;
    const int n0 = blockIdx.y * 128;

    const int base_m = (wid & 1) * 64;
    const int base_n = (wid >> 1) * 32;
    const int warp_n = wid >> 1;

    const uint32_t aA = smem_u32(sA), aB = smem_u32(sB);
    const uint32_t STB = STG_E * 2;

    const int r0c = tid >> 2, c0c = tid & 3;
    const int r1c = (tid + 256) >> 2, c1c = tid & 3;
    const uint32_t dOff0 = r0c * 80 + c0c * 16;
    const uint32_t dOff1 = r1c * 80 + c1c * 16;
    const size_t gA0 = (size_t)(m0 + r0c) * DDIM + c0c * 8;
    const size_t gA1 = (size_t)(m0 + r1c) * DDIM + c1c * 8;
    const size_t gB0 = (size_t)(n0 + r0c) * DDIM + c0c * 8;
    const size_t gB1 = (size_t)(n0 + r1c) * DDIM + c1c * 8;

    const uint32_t aOff = (uint32_t)(base_m + (lid & 7) + ((lid >> 3) & 1) * 8) * 80
                        + (uint32_t)(lid >> 4) * 16;
    const uint32_t bOff = (uint32_t)(base_n + (lid & 7) + ((lid >= 16) ? 8 : 0)) * 80
                        + (uint32_t)((lid >> 3) & 1) * 16;

    float c[4][4][4];
    #pragma unroll
    for (int i = 0; i < 4; i++)
        #pragma unroll
        for (int j = 0; j < 4; j++)
            #pragma unroll
            for (int k = 0; k < 4; k++) c[i][j][k] = 0.f;

    const int NKT = DDIM / BKS;  // 32

    cp16(aA + dOff0, (const char*)g_qbf + gA0 * 2);
    cp16(aA + dOff1, (const char*)g_qbf + gA1 * 2);
    cp16(aB + dOff0, (const char*)g_kbf + gB0 * 2);
    cp16(aB + dOff1, (const char*)g_kbf + gB1 * 2);
    cp_commit();

    for (int kt = 0; kt < NKT; kt++) {
        if (kt + 1 < NKT) {
            const uint32_t so = ((kt + 1) & 1) * STB;
            const size_t ko = (size_t)(kt + 1) * BKS;
            cp16(aA + so + dOff0, (const char*)g_qbf + (gA0 + ko) * 2);
            cp16(aA + so + dOff1, (const char*)g_qbf + (gA1 + ko) * 2);
            cp16(aB + so + dOff0, (const char*)g_kbf + (gB0 + ko) * 2);
            cp16(aB + so + dOff1, (const char*)g_kbf + (gB1 + ko) * 2);
        }
        cp_commit();
        cp_wait<1>();
        __syncthreads();

        const uint32_t so = (kt & 1) * STB;
        #pragma unroll
        for (int kk = 0; kk < 2; kk++) {
            const uint32_t ko = kk * 32;
            uint32_t ah[4][4], bh[2][4];
            #pragma unroll
            for (int mf = 0; mf < 4; mf++)
                ldm_x4(ah[mf], aA + so + aOff + ko + mf * (16 * 80));
            #pragma unroll
            for (int np = 0; np < 2; np++)
                ldm_x4(bh[np], aB + so + bOff + ko + np * (16 * 80));
            #pragma unroll
            for (int mf = 0; mf < 4; mf++)
                #pragma unroll
                for (int nf = 0; nf < 4; nf++)
                    mma_bf16(c[mf][nf], ah[mf], &bh[nf >> 1][(nf & 1) * 2]);
        }
        __syncthreads();
    }

    const int crow = lid >> 2;
    const int ccol = (lid & 3) * 2;

    // ---- per-row block max (warp covers 64 rows x 32 cols) -> smem
    float* rmax = reinterpret_cast<float*>(sA);   // 128 rows x 4 warp_n floats
    #pragma unroll
    for (int mf = 0; mf < 4; mf++) {
        float fm0 = fmaxf(c[mf][0][0], c[mf][0][1]);
        float fm1 = fmaxf(c[mf][0][2], c[mf][0][3]);
        #pragma unroll
        for (int nf = 1; nf < 4; nf++) {
            fm0 = fmaxf(fm0, fmaxf(c[mf][nf][0], c[mf][nf][1]));
            fm1 = fmaxf(fm1, fmaxf(c[mf][nf][2], c[mf][nf][3]));
        }
        fm0 = fmaxf(fm0, __shfl_xor_sync(0xffffffffu, fm0, 1));
        fm0 = fmaxf(fm0, __shfl_xor_sync(0xffffffffu, fm0, 2));
        fm1 = fmaxf(fm1, __shfl_xor_sync(0xffffffffu, fm1, 1));
        fm1 = fmaxf(fm1, __shfl_xor_sync(0xffffffffu, fm1, 2));
        if ((lid & 3) == 0) {
            rmax[(base_m + mf * 16 + crow) * 4 + warp_n] = fm0;
            rmax[(base_m + mf * 16 + crow + 8) * 4 + warp_n] = fm1;
        }
    }
    __syncthreads();
    if (tid < 128) {
        float v = fmaxf(fmaxf(rmax[tid * 4 + 0], rmax[tid * 4 + 1]),
                        fmaxf(rmax[tid * 4 + 2], rmax[tid * 4 + 3]));
        __nv_bfloat16 b = __float2bfloat16(v);
        g_bmax[(size_t)(m0 + tid) * NBLK + blockIdx.y] =
            *reinterpret_cast<unsigned short*>(&b);
    }

    // ---- bf16 scores
    #pragma unroll
    for (int mf = 0; mf < 4; mf++) {
        #pragma unroll
        for (int nf = 0; nf < 4; nf++) {
            int m = m0 + base_m + mf * 16 + crow;
            int n = n0 + base_n + nf * 8 + ccol;
            *reinterpret_cast<__nv_bfloat162*>(&g_sbf[(size_t)m * NKEY + n]) =
                __floats2bfloat162_rn(c[mf][nf][0], c[mf][nf][1]);
            *reinterpret_cast<__nv_bfloat162*>(&g_sbf[(size_t)(m + 8) * NKEY + n]) =
                __floats2bfloat162_rn(c[mf][nf][2], c[mf][nf][3]);
        }
    }
}

// ---------------------------------------------------------------------------
// Per-row topk: blockmax scan (1KB) -> b48 threshold -> scan ~48-60 selected
// 128-key blocks only -> deterministic top-48 (value, lower-index tiebreak)
// -> BIT-EXACT sequential-fma rescore -> rank -> softmax -> gather.
// ---------------------------------------------------------------------------
__global__ __launch_bounds__(128) void topk_out_kernel(
    const float* __restrict__ keys, const float* __restrict__ values,
    float* __restrict__ out)
{
    __shared__ float bmaxv[NBLK];
    __shared__ float wrk[NBLK];
    __shared__ int   blist[NBLK];
    __shared__ float cbufV[CAP2];
    __shared__ int   cbufI[CAP2];
    __shared__ __align__(16) float qrow[DDIM];
    __shared__ float rwv[4];
    __shared__ int   rws[4];
    __shared__ int   rwi[4];
    __shared__ float gthr;
    __shared__ int   bcnt_s, scnt;
    __shared__ int   ci[NCAND];
    __shared__ float rs[NCAND];
    __shared__ int   sidx[KSEL];
    __shared__ float ssc[KSEL];
    __shared__ float sw[KSEL];
    __shared__ float sZ;

    const int tid = threadIdx.x;
    const int lane = tid & 31, warp = tid >> 5;
    const int row = blockIdx.x;
    const __nv_bfloat16* srow = (const __nv_bfloat16*)g_sbf + (size_t)row * NKEY;

    // q row (fp32) for rescoring
    #pragma unroll
    for (int j = tid; j < DDIM / 4; j += 128)
        reinterpret_cast<float4*>(qrow)[j] =
            reinterpret_cast<const float4*>((const float*)g_q + (size_t)row * DDIM)[j];

    // ---- phase A: load blockmaxes; b48 = 48th largest (argmax rounds)
    #pragma unroll
    for (int j = tid; j < NBLK; j += 128) {
        uint32_t r = (uint32_t)g_bmax[(size_t)row * NBLK + j];
        float v = __uint_as_float(r << 16);
        bmaxv[j] = v; wrk[j] = v;
    }
    if (tid == 0) { bcnt_s = 0; scnt = 0; }
    __syncthreads();

    float thr = 0.f;
    for (int it = 0; it < NCAND; it++) {
        float best = -INFINITY; int bslot = 0;
        #pragma unroll
        for (int jj = tid; jj < NBLK; jj += 128) {
            float v = wrk[jj];
            if (v > best) { best = v; bslot = jj; }
        }
        #pragma unroll
        for (int o = 16; o > 0; o >>= 1) {
            float ov = __shfl_down_sync(0xffffffffu, best, o);
            int   os = __shfl_down_sync(0xffffffffu, bslot, o);
            if (ov > best) { best = ov; bslot = os; }
        }
        if (lane == 0) { rwv[warp] = best; rws[warp] = bslot; }
        __syncthreads();
        if (tid == 0) {
            float b = rwv[0]; int bs = rws[0];
            #pragma unroll
            for (int w = 1; w < 4; w++)
                if (rwv[w] > b) { b = rwv[w]; bs = rws[w]; }
            gthr = b;
            wrk[bs] = -INFINITY;
        }
        __syncthreads();
        thr = gthr;
    }

    // ---- build selected block list (membership deterministic)
    for (int j = tid; j < NBLK; j += 128)
        if (bmaxv[j] >= thr) { int p = atomicAdd(&bcnt_s, 1); blist[p] = j; }
    __syncthreads();
    const int bcnt = bcnt_s;

    // ---- phase B: scan only selected blocks, append keys >= thr
    for (int cch = tid; cch < bcnt * 16; cch += 128) {
        int b  = blist[cch >> 4];
        int ch = cch & 15;
        int base = b * 128 + ch * 8;
        uint4 raw = *reinterpret_cast<const uint4*>(srow + base);
        uint32_t ws[4] = {raw.x, raw.y, raw.z, raw.w};
        #pragma unroll
        for (int h = 0; h < 4; h++) {
            #pragma unroll
            for (int e = 0; e < 2; e++) {
                float v = __uint_as_float(e == 0 ? (ws[h] << 16)
                                                 : (ws[h] & 0xffff0000u));
                if (v >= thr) {
                    int pos = atomicAdd(&scnt, 1);
                    if (pos < CAP2) { cbufV[pos] = v; cbufI[pos] = base + h * 2 + e; }
                }
            }
        }
    }
    __syncthreads();
    const int m = min(scnt, CAP2);

    // ---- phase C: deterministic top-48 (value desc, lower index tiebreak)
    for (int it = 0; it < NCAND; it++) {
        float best = -INFINITY; int bslot = -1; int bidx = 0x7fffffff;
        for (int jj = tid; jj < m; jj += 128) {
            float v = cbufV[jj];
            int   ix = cbufI[jj];
            if (v > best || (v == best && ix < bidx)) { best = v; bslot = jj; bidx = ix; }
        }
        #pragma unroll
        for (int o = 16; o > 0; o >>= 1) {
            float ov = __shfl_down_sync(0xffffffffu, best, o);
            int   os = __shfl_down_sync(0xffffffffu, bslot, o);
            int   oi = __shfl_down_sync(0xffffffffu, bidx, o);
            if (ov > best || (ov == best && oi < bidx)) { best = ov; bslot = os; bidx = oi; }
        }
        if (lane == 0) { rwv[warp] = best; rws[warp] = bslot; rwi[warp] = bidx; }
        __syncthreads();
        if (tid == 0) {
            float b = rwv[0]; int bs = rws[0]; int bi = rwi[0];
            #pragma unroll
            for (int w = 1; w < 4; w++)
                if (rwv[w] > b || (rwv[w] == b && rwi[w] < bi)) {
                    b = rwv[w]; bs = rws[w]; bi = rwi[w];
                }
            if (bs >= 0) { ci[it] = cbufI[bs]; cbufV[bs] = -INFINITY; }
            else         { ci[it] = -(it + 1); }
        }
        __syncthreads();
    }

    // ---- phase D: BIT-EXACT rescore (sequential rn-fma, k ascending)
    if (tid < NCAND) {
        int cidx = ci[tid];
        if (cidx >= 0) {
            const float* krow = keys + (size_t)cidx * DDIM;
            float acc = 0.f;
            #pragma unroll 8
            for (int k = 0; k < DDIM; k++)
                acc = __fmaf_rn(qrow[k], __ldg(&krow[k]), acc);
            rs[tid] = acc;
        } else {
            rs[tid] = -INFINITY;
        }
    }
    __syncthreads();

    // exact rank with stable (lower-index-first) tie-break; select top-32
    if (tid < NCAND) {
        float sc = rs[tid];
        int   myi = ci[tid];
        int rank = 0;
        #pragma unroll
        for (int j = 0; j < NCAND; j++) {
            float sj = rs[j];
            rank += (sj > sc) || (sj == sc && ci[j] < myi);
        }
        if (rank < KSEL) { sidx[rank] = myi; ssc[rank] = sc; }
    }
    __syncthreads();

    // softmax over exact top-32 (TEMP=1); ssc[0] is the max
    if (tid < KSEL) sw[tid] = expf(ssc[tid] - ssc[0]);
    __syncthreads();
    if (tid == 0) {
        float z = 0.f;
        #pragma unroll
        for (int j = 0; j < KSEL; j++) z += sw[j];
        sZ = z;
    }
    __syncthreads();
    const float invZ = 1.0f / sZ;

    // weighted gather of values rows (GATING=1)
    for (int d = tid; d < DDIM; d += 128) {
        float acc = 0.f;
        #pragma unroll 8
        for (int k = 0; k < KSEL; k++)
            acc += sw[k] * values[(size_t)sidx[k] * DDIM + d];
        out[(size_t)row * DDIM + d] = acc * invZ;
    }
}

// ---------------------------------------------------------------------------
extern "C" void kernel_launch(void* const* d_in, const int* in_sizes, int n_in,
                              void* d_out, int out_size) {
    const float* x      = (const float*)d_in[0];
    const float* q_w    = (const float*)d_in[1];
    const float* keys   = (const float*)d_in[2];
    const float* values = (const float*)d_in[3];
    float* out = (float*)d_out;

    cudaStream_t st = cudaStreamPerThread;

    // 1) q = x @ q_w^T -> g_q (fp32) + g_qbf (bf16 mirror)
    dim3 g1(NROWS / BM, DDIM / BN);
    gemm_qproj_kernel<<<g1, 256, 0, st>>>(x, q_w, NROWS, DDIM, DDIM);

    // 2) keys -> bf16
    cvt_keys_kernel<<<(int)(((size_t)NKEY * DDIM / 4) / 256), 256, 0, st>>>(keys);

    // 3) approx scores + per-block maxima via bf16 mma
    dim3 g2(NROWS / 128, NKEY / 128);
    scores_mma_kernel<<<g2, 256, 0, st>>>();

    // 4) blockmax-filtered candidates + bit-exact rescore + softmax + gather
    topk_out_kernel<<<NROWS, 128, 0, st>>>(keys, values, out);
}

// round 13
// speedup vs baseline: 4.6828x; 1.0880x over previous
#include <cuda_runtime.h>
#include <cuda_bf16.h>
#include <cstdint>

#define NROWS 4096
#define DDIM  1024
#define NKEY  65536
#define KSEL  32
#define NCAND 48
#define NBLK  512          // NKEY / 128 score blocks per row
#define CAP2  2048

// ---------------------------------------------------------------------------
// Static device scratch (allocation-guard safe). NEVER passed as host-side
// kernel args (host shadow trap!) — referenced from device code only.
// ---------------------------------------------------------------------------
__device__ float g_q[(size_t)NROWS * DDIM];                 // 16 MB (fp32 q)
__device__ __nv_bfloat16 g_qbf[(size_t)NROWS * DDIM];       // 8 MB
__device__ __nv_bfloat16 g_kbf[(size_t)NKEY * DDIM];        // 128 MB
__device__ __nv_bfloat16 g_sbf[(size_t)NROWS * NKEY];       // 512 MB (bf16 scores)
__device__ unsigned short g_bmax[(size_t)NROWS * NBLK];     // 4 MB (per-block max)

// ---------------------------------------------------------------------------
// Packed f32x2 helpers (qproj fp32 GEMM)
// ---------------------------------------------------------------------------
__device__ __forceinline__ unsigned long long bcast2(float a) {
    unsigned long long r;
    unsigned int ai = __float_as_uint(a);
    asm("mov.b64 %0, {%1, %1};" : "=l"(r) : "r"(ai));
    return r;
}
__device__ __forceinline__ void fma2(unsigned long long& d,
                                     unsigned long long a,
                                     unsigned long long b) {
    asm("fma.rn.f32x2 %0, %1, %2, %0;" : "+l"(d) : "l"(a), "l"(b));
}

__device__ __forceinline__ uint32_t smem_u32(const void* p) {
    uint32_t a;
    asm("{ .reg .u64 t; cvta.to.shared.u64 t, %1; cvt.u32.u64 %0, t; }"
        : "=r"(a) : "l"(p));
    return a;
}

// mma.sync / ldmatrix / cp.async (baseline ISA, valid on plain sm_103 target)
__device__ __forceinline__ void ldm_x4(uint32_t* r, uint32_t addr) {
    asm volatile("ldmatrix.sync.aligned.m8n8.x4.shared.b16 {%0,%1,%2,%3}, [%4];"
        : "=r"(r[0]), "=r"(r[1]), "=r"(r[2]), "=r"(r[3]) : "r"(addr));
}
__device__ __forceinline__ void mma_bf16(float* c, const uint32_t* a,
                                         const uint32_t* b) {
    asm volatile(
        "mma.sync.aligned.m16n8k16.row.col.f32.bf16.bf16.f32 "
        "{%0,%1,%2,%3}, {%4,%5,%6,%7}, {%8,%9}, {%0,%1,%2,%3};"
        : "+f"(c[0]), "+f"(c[1]), "+f"(c[2]), "+f"(c[3])
        : "r"(a[0]), "r"(a[1]), "r"(a[2]), "r"(a[3]), "r"(b[0]), "r"(b[1]));
}
__device__ __forceinline__ void cp16(uint32_t dst, const void* src) {
    asm volatile("cp.async.cg.shared.global [%0], [%1], 16;"
        :: "r"(dst), "l"(src));
}
__device__ __forceinline__ void cp_commit() {
    asm volatile("cp.async.commit_group;");
}
template <int N>
__device__ __forceinline__ void cp_wait() {
    asm volatile("cp.async.wait_group %0;" :: "n"(N) : "memory");
}

// ---------------------------------------------------------------------------
// qproj: g_q = x @ q_w^T (4096x1024x1024), fp32, BM=BN=128, BK=16.
// Epilogue also emits bf16 copy into g_qbf.
// ---------------------------------------------------------------------------
#define BM 128
#define BN 128
#define BK 16

__global__ __launch_bounds__(256) void gemm_qproj_kernel(
    const float* __restrict__ A, const float* __restrict__ B, int M, int N, int K)
{
    float* __restrict__ C = (float*)g_q;
    __nv_bfloat16* __restrict__ Cbf = (__nv_bfloat16*)g_qbf;
    __shared__ __align__(16) float As[BK][BM];
    __shared__ __align__(16) float Bs[BK][BN];
    const int tid = threadIdx.x;
    const int tx = tid & 15;
    const int ty = tid >> 4;
    const int m0 = blockIdx.x * BM;
    const int n0 = blockIdx.y * BN;

    unsigned long long acc[8][4];
    #pragma unroll
    for (int i = 0; i < 8; i++)
        #pragma unroll
        for (int j = 0; j < 4; j++) acc[i][j] = 0ull;

    for (int kt = 0; kt < K; kt += BK) {
        #pragma unroll
        for (int p = 0; p < 2; p++) {
            int i = tid + p * 256;
            int row = i >> 2;
            int kq  = (i & 3) << 2;
            float4 av = *reinterpret_cast<const float4*>(
                &A[(size_t)(m0 + row) * K + kt + kq]);
            As[kq + 0][row] = av.x; As[kq + 1][row] = av.y;
            As[kq + 2][row] = av.z; As[kq + 3][row] = av.w;
            float4 bv = *reinterpret_cast<const float4*>(
                &B[(size_t)(n0 + row) * K + kt + kq]);
            Bs[kq + 0][row] = bv.x; Bs[kq + 1][row] = bv.y;
            Bs[kq + 2][row] = bv.z; Bs[kq + 3][row] = bv.w;
        }
        __syncthreads();
        #pragma unroll
        for (int k = 0; k < BK; k++) {
            float a[8];
            *reinterpret_cast<float4*>(&a[0]) =
                *reinterpret_cast<const float4*>(&As[k][ty * 4]);
            *reinterpret_cast<float4*>(&a[4]) =
                *reinterpret_cast<const float4*>(&As[k][ty * 4 + 64]);
            ulonglong2 b01 = *reinterpret_cast<const ulonglong2*>(&Bs[k][tx * 4]);
            ulonglong2 b23 = *reinterpret_cast<const ulonglong2*>(&Bs[k][tx * 4 + 64]);
            #pragma unroll
            for (int i = 0; i < 8; i++) {
                unsigned long long ab = bcast2(a[i]);
                fma2(acc[i][0], ab, b01.x);
                fma2(acc[i][1], ab, b01.y);
                fma2(acc[i][2], ab, b23.x);
                fma2(acc[i][3], ab, b23.y);
            }
        }
        __syncthreads();
    }

    #pragma unroll
    for (int i = 0; i < 8; i++) {
        int m = m0 + ty * 4 + (i < 4 ? i : 60 + i);
        float2 c0 = *reinterpret_cast<float2*>(&acc[i][0]);
        float2 c1 = *reinterpret_cast<float2*>(&acc[i][1]);
        float2 c2 = *reinterpret_cast<float2*>(&acc[i][2]);
        float2 c3 = *reinterpret_cast<float2*>(&acc[i][3]);
        *reinterpret_cast<float4*>(&C[(size_t)m * N + n0 + tx * 4]) =
            make_float4(c0.x, c0.y, c1.x, c1.y);
        *reinterpret_cast<float4*>(&C[(size_t)m * N + n0 + 64 + tx * 4]) =
            make_float4(c2.x, c2.y, c3.x, c3.y);
        __nv_bfloat162 p0 = __floats2bfloat162_rn(c0.x, c0.y);
        __nv_bfloat162 p1 = __floats2bfloat162_rn(c1.x, c1.y);
        __nv_bfloat162 p2 = __floats2bfloat162_rn(c2.x, c2.y);
        __nv_bfloat162 p3 = __floats2bfloat162_rn(c3.x, c3.y);
        *reinterpret_cast<__nv_bfloat162*>(&Cbf[(size_t)m * N + n0 + tx * 4]) = p0;
        *reinterpret_cast<__nv_bfloat162*>(&Cbf[(size_t)m * N + n0 + tx * 4 + 2]) = p1;
        *reinterpret_cast<__nv_bfloat162*>(&Cbf[(size_t)m * N + n0 + 64 + tx * 4]) = p2;
        *reinterpret_cast<__nv_bfloat162*>(&Cbf[(size_t)m * N + n0 + 64 + tx * 4 + 2]) = p3;
    }
}

// ---------------------------------------------------------------------------
// keys fp32 -> bf16
// ---------------------------------------------------------------------------
__global__ __launch_bounds__(256) void cvt_keys_kernel(const float* __restrict__ src)
{
    __nv_bfloat16* __restrict__ dst = (__nv_bfloat16*)g_kbf;
    size_t i = (size_t)blockIdx.x * 256 + threadIdx.x;   // float4 index
    float4 v = reinterpret_cast<const float4*>(src)[i];
    __nv_bfloat162 p0 = __floats2bfloat162_rn(v.x, v.y);
    __nv_bfloat162 p1 = __floats2bfloat162_rn(v.z, v.w);
    __nv_bfloat162* dp = reinterpret_cast<__nv_bfloat162*>(dst) + 2 * i;
    dp[0] = p0; dp[1] = p1;
}

// ---------------------------------------------------------------------------
// approx scores = q_bf @ keys_bf^T via mma.sync -> bf16 + per-block maxima.
// Tile 128x256, BK=32, 2-stage double buffer, 8 warps as 2(m)x4(n) = 64x64.
// Unpadded 64B rows + XOR swizzle chunk' = chunk ^ ((row>>1)&3):
// every 8-lane ldmatrix phase hits 8 distinct bank groups. smem = 48KB exactly.
// Per 16-k: 4 A-ldm + 4 B-ldm -> 32 mma per warp (k ascending per accumulator
// => scores bit-identical to previous rounds).
// ---------------------------------------------------------------------------
#define TM2 128
#define TN2 256
#define BKS 32
#define A_STG 8192            // bytes per A stage (128 rows x 64B)
#define B_STG 16384           // bytes per B stage (256 rows x 64B)

__global__ __launch_bounds__(256, 1) void scores_mma_kernel()
{
    __shared__ __align__(16) unsigned char sA[2 * A_STG];   // 16 KB
    __shared__ __align__(16) unsigned char sB[2 * B_STG];   // 32 KB

    const int tid = threadIdx.x;
    const int wid = tid >> 5;
    const int lid = tid & 31;
    const int m0 = blockIdx.x * TM2;
    const int n0 = blockIdx.y * TN2;

    const int base_m = (wid & 1) * 64;
    const int warp_n = wid >> 1;           // 0..3
    const int base_n = warp_n * 64;

    const uint32_t aA = smem_u32(sA), aB = smem_u32(sB);

    // ---- cp.async chunk mapping (16B chunks, 4 per 64B row), swizzled
    const int rA0 = tid >> 2,          cA0 = tid & 3;
    const int rA1 = (tid + 256) >> 2,  cA1 = tid & 3;
    const uint32_t dA0 = rA0 * 64 + ((cA0 ^ ((rA0 >> 1) & 3)) << 4);
    const uint32_t dA1 = rA1 * 64 + ((cA1 ^ ((rA1 >> 1) & 3)) << 4);
    const size_t sA0 = (size_t)(m0 + rA0) * DDIM + cA0 * 8;
    const size_t sA1 = (size_t)(m0 + rA1) * DDIM + cA1 * 8;
    uint32_t dB[4]; size_t sBo[4];
    #pragma unroll
    for (int j = 0; j < 4; j++) {
        int cc = tid + j * 256;
        int rB = cc >> 2, cB = cc & 3;
        dB[j] = rB * 64 + ((cB ^ ((rB >> 1) & 3)) << 4);
        sBo[j] = (size_t)(n0 + rB) * DDIM + cB * 8;
    }

    // ---- ldmatrix lane geometry (rows fixed, chunk varies with kk)
    const int aRow = base_m + (lid & 7) + ((lid >> 3) & 1) * 8;
    const int aSw  = (aRow >> 1) & 3;
    const int aChBase = (lid >> 4);            // 0/1
    const int bRow = base_n + (lid & 7) + ((lid >= 16) ? 8 : 0);
    const int bSw  = (bRow >> 1) & 3;
    const int bChBase = (lid >> 3) & 1;        // 0/1

    float c[4][8][4];
    #pragma unroll
    for (int i = 0; i < 4; i++)
        #pragma unroll
        for (int j = 0; j < 8; j++)
            #pragma unroll
            for (int k = 0; k < 4; k++) c[i][j][k] = 0.f;

    const int NKT = DDIM / BKS;  // 32

    // prologue: stage 0
    cp16(aA + dA0, (const char*)g_qbf + sA0 * 2);
    cp16(aA + dA1, (const char*)g_qbf + sA1 * 2);
    #pragma unroll
    for (int j = 0; j < 4; j++)
        cp16(aB + dB[j], (const char*)g_kbf + sBo[j] * 2);
    cp_commit();

    for (int kt = 0; kt < NKT; kt++) {
        if (kt + 1 < NKT) {
            const uint32_t soA = ((kt + 1) & 1) * A_STG;
            const uint32_t soB = ((kt + 1) & 1) * B_STG;
            const size_t ko = (size_t)(kt + 1) * BKS;
            cp16(aA + soA + dA0, (const char*)g_qbf + (sA0 + ko) * 2);
            cp16(aA + soA + dA1, (const char*)g_qbf + (sA1 + ko) * 2);
            #pragma unroll
            for (int j = 0; j < 4; j++)
                cp16(aB + soB + dB[j], (const char*)g_kbf + (sBo[j] + ko) * 2);
        }
        cp_commit();
        cp_wait<1>();
        __syncthreads();

        const uint32_t soA = (kt & 1) * A_STG;
        const uint32_t soB = (kt & 1) * B_STG;
        #pragma unroll
        for (int kk = 0; kk < 2; kk++) {      // k ascending within stage
            uint32_t ah[4][4], bh[4][4];
            const int aCh = ((kk * 2 + aChBase) ^ aSw) << 4;
            const int bCh = ((kk * 2 + bChBase) ^ bSw) << 4;
            #pragma unroll
            for (int mf = 0; mf < 4; mf++)
                ldm_x4(ah[mf], aA + soA + (uint32_t)(aRow + mf * 16) * 64 + aCh);
            #pragma unroll
            for (int np = 0; np < 4; np++)
                ldm_x4(bh[np], aB + soB + (uint32_t)(bRow + np * 16) * 64 + bCh);
            #pragma unroll
            for (int mf = 0; mf < 4; mf++)
                #pragma unroll
                for (int nf = 0; nf < 8; nf++)
                    mma_bf16(c[mf][nf], ah[mf], &bh[nf >> 1][(nf & 1) * 2]);
        }
        __syncthreads();
    }

    const int crow = lid >> 2;
    const int ccol = (lid & 3) * 2;

    // ---- per-row block max (warp covers 64 rows x 64 cols) -> smem
    float* rmax = reinterpret_cast<float*>(sA);   // 128 rows x 4 warp_n
    #pragma unroll
    for (int mf = 0; mf < 4; mf++) {
        float fm0 = -INFINITY, fm1 = -INFINITY;
        #pragma unroll
        for (int nf = 0; nf < 8; nf++) {
            fm0 = fmaxf(fm0, fmaxf(c[mf][nf][0], c[mf][nf][1]));
            fm1 = fmaxf(fm1, fmaxf(c[mf][nf][2], c[mf][nf][3]));
        }
        fm0 = fmaxf(fm0, __shfl_xor_sync(0xffffffffu, fm0, 1));
        fm0 = fmaxf(fm0, __shfl_xor_sync(0xffffffffu, fm0, 2));
        fm1 = fmaxf(fm1, __shfl_xor_sync(0xffffffffu, fm1, 1));
        fm1 = fmaxf(fm1, __shfl_xor_sync(0xffffffffu, fm1, 2));
        if ((lid & 3) == 0) {
            rmax[(base_m + mf * 16 + crow) * 4 + warp_n] = fm0;
            rmax[(base_m + mf * 16 + crow + 8) * 4 + warp_n] = fm1;
        }
    }
    __syncthreads();
    if (tid < 128) {
        float v0 = fmaxf(rmax[tid * 4 + 0], rmax[tid * 4 + 1]);   // cols 0..127
        float v1 = fmaxf(rmax[tid * 4 + 2], rmax[tid * 4 + 3]);   // cols 128..255
        __nv_bfloat16 b0 = __float2bfloat16(v0);
        __nv_bfloat16 b1 = __float2bfloat16(v1);
        g_bmax[(size_t)(m0 + tid) * NBLK + blockIdx.y * 2 + 0] =
            *reinterpret_cast<unsigned short*>(&b0);
        g_bmax[(size_t)(m0 + tid) * NBLK + blockIdx.y * 2 + 1] =
            *reinterpret_cast<unsigned short*>(&b1);
    }

    // ---- bf16 scores
    #pragma unroll
    for (int mf = 0; mf < 4; mf++) {
        #pragma unroll
        for (int nf = 0; nf < 8; nf++) {
            int m = m0 + base_m + mf * 16 + crow;
            int n = n0 + base_n + nf * 8 + ccol;
            *reinterpret_cast<__nv_bfloat162*>(&g_sbf[(size_t)m * NKEY + n]) =
                __floats2bfloat162_rn(c[mf][nf][0], c[mf][nf][1]);
            *reinterpret_cast<__nv_bfloat162*>(&g_sbf[(size_t)(m + 8) * NKEY + n]) =
                __floats2bfloat162_rn(c[mf][nf][2], c[mf][nf][3]);
        }
    }
}

// ---------------------------------------------------------------------------
// Per-row topk: blockmax scan (1KB) -> b48 threshold -> scan selected 128-key
// blocks only -> deterministic top-48 (value, lower-index tiebreak)
// -> BIT-EXACT sequential-fma rescore -> rank -> softmax -> gather.
// ---------------------------------------------------------------------------
__global__ __launch_bounds__(128) void topk_out_kernel(
    const float* __restrict__ keys, const float* __restrict__ values,
    float* __restrict__ out)
{
    __shared__ float bmaxv[NBLK];
    __shared__ float wrk[NBLK];
    __shared__ int   blist[NBLK];
    __shared__ float cbufV[CAP2];
    __shared__ int   cbufI[CAP2];
    __shared__ __align__(16) float qrow[DDIM];
    __shared__ float rwv[4];
    __shared__ int   rws[4];
    __shared__ int   rwi[4];
    __shared__ float gthr;
    __shared__ int   bcnt_s, scnt;
    __shared__ int   ci[NCAND];
    __shared__ float rs[NCAND];
    __shared__ int   sidx[KSEL];
    __shared__ float ssc[KSEL];
    __shared__ float sw[KSEL];
    __shared__ float sZ;

    const int tid = threadIdx.x;
    const int lane = tid & 31, warp = tid >> 5;
    const int row = blockIdx.x;
    const __nv_bfloat16* srow = (const __nv_bfloat16*)g_sbf + (size_t)row * NKEY;

    #pragma unroll
    for (int j = tid; j < DDIM / 4; j += 128)
        reinterpret_cast<float4*>(qrow)[j] =
            reinterpret_cast<const float4*>((const float*)g_q + (size_t)row * DDIM)[j];

    // ---- phase A: load blockmaxes; thr = 48th largest (argmax rounds)
    #pragma unroll
    for (int j = tid; j < NBLK; j += 128) {
        uint32_t r = (uint32_t)g_bmax[(size_t)row * NBLK + j];
        float v = __uint_as_float(r << 16);
        bmaxv[j] = v; wrk[j] = v;
    }
    if (tid == 0) { bcnt_s = 0; scnt = 0; }
    __syncthreads();

    float thr = 0.f;
    for (int it = 0; it < NCAND; it++) {
        float best = -INFINITY; int bslot = 0;
        #pragma unroll
        for (int jj = tid; jj < NBLK; jj += 128) {
            float v = wrk[jj];
            if (v > best) { best = v; bslot = jj; }
        }
        #pragma unroll
        for (int o = 16; o > 0; o >>= 1) {
            float ov = __shfl_down_sync(0xffffffffu, best, o);
            int   os = __shfl_down_sync(0xffffffffu, bslot, o);
            if (ov > best) { best = ov; bslot = os; }
        }
        if (lane == 0) { rwv[warp] = best; rws[warp] = bslot; }
        __syncthreads();
        if (tid == 0) {
            float b = rwv[0]; int bs = rws[0];
            #pragma unroll
            for (int w = 1; w < 4; w++)
                if (rwv[w] > b) { b = rwv[w]; bs = rws[w]; }
            gthr = b;
            wrk[bs] = -INFINITY;
        }
        __syncthreads();
        thr = gthr;
    }

    for (int j = tid; j < NBLK; j += 128)
        if (bmaxv[j] >= thr) { int p = atomicAdd(&bcnt_s, 1); blist[p] = j; }
    __syncthreads();
    const int bcnt = bcnt_s;

    // ---- phase B: scan only selected blocks, append keys >= thr
    for (int cch = tid; cch < bcnt * 16; cch += 128) {
        int b  = blist[cch >> 4];
        int ch = cch & 15;
        int base = b * 128 + ch * 8;
        uint4 raw = *reinterpret_cast<const uint4*>(srow + base);
        uint32_t ws[4] = {raw.x, raw.y, raw.z, raw.w};
        #pragma unroll
        for (int h = 0; h < 4; h++) {
            #pragma unroll
            for (int e = 0; e < 2; e++) {
                float v = __uint_as_float(e == 0 ? (ws[h] << 16)
                                                 : (ws[h] & 0xffff0000u));
                if (v >= thr) {
                    int pos = atomicAdd(&scnt, 1);
                    if (pos < CAP2) { cbufV[pos] = v; cbufI[pos] = base + h * 2 + e; }
                }
            }
        }
    }
    __syncthreads();
    const int m = min(scnt, CAP2);

    // ---- phase C: deterministic top-48 (value desc, lower index tiebreak)
    for (int it = 0; it < NCAND; it++) {
        float best = -INFINITY; int bslot = -1; int bidx = 0x7fffffff;
        for (int jj = tid; jj < m; jj += 128) {
            float v = cbufV[jj];
            int   ix = cbufI[jj];
            if (v > best || (v == best && ix < bidx)) { best = v; bslot = jj; bidx = ix; }
        }
        #pragma unroll
        for (int o = 16; o > 0; o >>= 1) {
            float ov = __shfl_down_sync(0xffffffffu, best, o);
            int   os = __shfl_down_sync(0xffffffffu, bslot, o);
            int   oi = __shfl_down_sync(0xffffffffu, bidx, o);
            if (ov > best || (ov == best && oi < bidx)) { best = ov; bslot = os; bidx = oi; }
        }
        if (lane == 0) { rwv[warp] = best; rws[warp] = bslot; rwi[warp] = bidx; }
        __syncthreads();
        if (tid == 0) {
            float b = rwv[0]; int bs = rws[0]; int bi = rwi[0];
            #pragma unroll
            for (int w = 1; w < 4; w++)
                if (rwv[w] > b || (rwv[w] == b && rwi[w] < bi)) {
                    b = rwv[w]; bs = rws[w]; bi = rwi[w];
                }
            if (bs >= 0) { ci[it] = cbufI[bs]; cbufV[bs] = -INFINITY; }
            else         { ci[it] = -(it + 1); }
        }
        __syncthreads();
    }

    // ---- phase D: BIT-EXACT rescore (sequential rn-fma, k ascending)
    if (tid < NCAND) {
        int cidx = ci[tid];
        if (cidx >= 0) {
            const float* krow = keys + (size_t)cidx * DDIM;
            float acc = 0.f;
            #pragma unroll 8
            for (int k = 0; k < DDIM; k++)
                acc = __fmaf_rn(qrow[k], __ldg(&krow[k]), acc);
            rs[tid] = acc;
        } else {
            rs[tid] = -INFINITY;
        }
    }
    __syncthreads();

    if (tid < NCAND) {
        float sc = rs[tid];
        int   myi = ci[tid];
        int rank = 0;
        #pragma unroll
        for (int j = 0; j < NCAND; j++) {
            float sj = rs[j];
            rank += (sj > sc) || (sj == sc && ci[j] < myi);
        }
        if (rank < KSEL) { sidx[rank] = myi; ssc[rank] = sc; }
    }
    __syncthreads();

    if (tid < KSEL) sw[tid] = expf(ssc[tid] - ssc[0]);
    __syncthreads();
    if (tid == 0) {
        float z = 0.f;
        #pragma unroll
        for (int j = 0; j < KSEL; j++) z += sw[j];
        sZ = z;
    }
    __syncthreads();
    const float invZ = 1.0f / sZ;

    for (int d = tid; d < DDIM; d += 128) {
        float acc = 0.f;
        #pragma unroll 8
        for (int k = 0; k < KSEL; k++)
            acc += sw[k] * values[(size_t)sidx[k] * DDIM + d];
        out[(size_t)row * DDIM + d] = acc * invZ;
    }
}

// ---------------------------------------------------------------------------
extern "C" void kernel_launch(void* const* d_in, const int* in_sizes, int n_in,
                              void* d_out, int out_size) {
    const float* x      = (const float*)d_in[0];
    const float* q_w    = (const float*)d_in[1];
    const float* keys   = (const float*)d_in[2];
    const float* values = (const float*)d_in[3];
    float* out = (float*)d_out;

    cudaStream_t st = cudaStreamPerThread;

    // 1) q = x @ q_w^T -> g_q (fp32) + g_qbf (bf16 mirror)
    dim3 g1(NROWS / BM, DDIM / BN);
    gemm_qproj_kernel<<<g1, 256, 0, st>>>(x, q_w, NROWS, DDIM, DDIM);

    // 2) keys -> bf16
    cvt_keys_kernel<<<(int)(((size_t)NKEY * DDIM / 4) / 256), 256, 0, st>>>(keys);

    // 3) approx scores + per-block maxima via bf16 mma (128x256 tiles)
    dim3 g2(NROWS / TM2, NKEY / TN2);
    scores_mma_kernel<<<g2, 256, 0, st>>>();

    // 4) blockmax-filtered candidates + bit-exact rescore + softmax + gather
    topk_out_kernel<<<NROWS, 128, 0, st>>>(keys, values, out);
}

// round 14
// speedup vs baseline: 6.1682x; 1.3172x over previous
#include <cuda_runtime.h>
#include <cuda_bf16.h>
#include <cstdint>

#define NROWS 4096
#define DDIM  1024
#define NKEY  65536
#define KSEL  32
#define NCAND 48
#define NBLK  512          // NKEY / 128 score blocks per row
#define CAP2  768

// ---------------------------------------------------------------------------
// Static device scratch (allocation-guard safe). NEVER passed as host-side
// kernel args (host shadow trap!) — referenced from device code only.
// ---------------------------------------------------------------------------
__device__ float g_q[(size_t)NROWS * DDIM];                 // 16 MB (fp32 q)
__device__ __nv_bfloat16 g_qbf[(size_t)NROWS * DDIM];       // 8 MB
__device__ __nv_bfloat16 g_kbf[(size_t)NKEY * DDIM];        // 128 MB
__device__ __nv_bfloat16 g_sbf[(size_t)NROWS * NKEY];       // 512 MB (bf16 scores)
__device__ unsigned short g_bmax[(size_t)NROWS * NBLK];     // 4 MB (per-block max)

// ---------------------------------------------------------------------------
// Packed f32x2 helpers (qproj fp32 GEMM)
// ---------------------------------------------------------------------------
__device__ __forceinline__ unsigned long long bcast2(float a) {
    unsigned long long r;
    unsigned int ai = __float_as_uint(a);
    asm("mov.b64 %0, {%1, %1};" : "=l"(r) : "r"(ai));
    return r;
}
__device__ __forceinline__ void fma2(unsigned long long& d,
                                     unsigned long long a,
                                     unsigned long long b) {
    asm("fma.rn.f32x2 %0, %1, %2, %0;" : "+l"(d) : "l"(a), "l"(b));
}

__device__ __forceinline__ uint32_t smem_u32(const void* p) {
    uint32_t a;
    asm("{ .reg .u64 t; cvta.to.shared.u64 t, %1; cvt.u32.u64 %0, t; }"
        : "=r"(a) : "l"(p));
    return a;
}

// mma.sync / ldmatrix / cp.async (baseline ISA, valid on plain sm_103 target)
__device__ __forceinline__ void ldm_x4(uint32_t* r, uint32_t addr) {
    asm volatile("ldmatrix.sync.aligned.m8n8.x4.shared.b16 {%0,%1,%2,%3}, [%4];"
        : "=r"(r[0]), "=r"(r[1]), "=r"(r[2]), "=r"(r[3]) : "r"(addr));
}
__device__ __forceinline__ void mma_bf16(float* c, const uint32_t* a,
                                         const uint32_t* b) {
    asm volatile(
        "mma.sync.aligned.m16n8k16.row.col.f32.bf16.bf16.f32 "
        "{%0,%1,%2,%3}, {%4,%5,%6,%7}, {%8,%9}, {%0,%1,%2,%3};"
        : "+f"(c[0]), "+f"(c[1]), "+f"(c[2]), "+f"(c[3])
        : "r"(a[0]), "r"(a[1]), "r"(a[2]), "r"(a[3]), "r"(b[0]), "r"(b[1]));
}
__device__ __forceinline__ void cp16(uint32_t dst, const void* src) {
    asm volatile("cp.async.cg.shared.global [%0], [%1], 16;"
        :: "r"(dst), "l"(src));
}
__device__ __forceinline__ void cp_commit() {
    asm volatile("cp.async.commit_group;");
}
template <int N>
__device__ __forceinline__ void cp_wait() {
    asm volatile("cp.async.wait_group %0;" :: "n"(N) : "memory");
}

// ---------------------------------------------------------------------------
// qproj: g_q = x @ q_w^T (4096x1024x1024), fp32, BM=BN=128, BK=16.
// Epilogue also emits bf16 copy into g_qbf.
// ---------------------------------------------------------------------------
#define BM 128
#define BN 128
#define BK 16

__global__ __launch_bounds__(256) void gemm_qproj_kernel(
    const float* __restrict__ A, const float* __restrict__ B, int M, int N, int K)
{
    float* __restrict__ C = (float*)g_q;
    __nv_bfloat16* __restrict__ Cbf = (__nv_bfloat16*)g_qbf;
    __shared__ __align__(16) float As[BK][BM];
    __shared__ __align__(16) float Bs[BK][BN];
    const int tid = threadIdx.x;
    const int tx = tid & 15;
    const int ty = tid >> 4;
    const int m0 = blockIdx.x * BM;
    const int n0 = blockIdx.y * BN;

    unsigned long long acc[8][4];
    #pragma unroll
    for (int i = 0; i < 8; i++)
        #pragma unroll
        for (int j = 0; j < 4; j++) acc[i][j] = 0ull;

    for (int kt = 0; kt < K; kt += BK) {
        #pragma unroll
        for (int p = 0; p < 2; p++) {
            int i = tid + p * 256;
            int row = i >> 2;
            int kq  = (i & 3) << 2;
            float4 av = *reinterpret_cast<const float4*>(
                &A[(size_t)(m0 + row) * K + kt + kq]);
            As[kq + 0][row] = av.x; As[kq + 1][row] = av.y;
            As[kq + 2][row] = av.z; As[kq + 3][row] = av.w;
            float4 bv = *reinterpret_cast<const float4*>(
                &B[(size_t)(n0 + row) * K + kt + kq]);
            Bs[kq + 0][row] = bv.x; Bs[kq + 1][row] = bv.y;
            Bs[kq + 2][row] = bv.z; Bs[kq + 3][row] = bv.w;
        }
        __syncthreads();
        #pragma unroll
        for (int k = 0; k < BK; k++) {
            float a[8];
            *reinterpret_cast<float4*>(&a[0]) =
                *reinterpret_cast<const float4*>(&As[k][ty * 4]);
            *reinterpret_cast<float4*>(&a[4]) =
                *reinterpret_cast<const float4*>(&As[k][ty * 4 + 64]);
            ulonglong2 b01 = *reinterpret_cast<const ulonglong2*>(&Bs[k][tx * 4]);
            ulonglong2 b23 = *reinterpret_cast<const ulonglong2*>(&Bs[k][tx * 4 + 64]);
            #pragma unroll
            for (int i = 0; i < 8; i++) {
                unsigned long long ab = bcast2(a[i]);
                fma2(acc[i][0], ab, b01.x);
                fma2(acc[i][1], ab, b01.y);
                fma2(acc[i][2], ab, b23.x);
                fma2(acc[i][3], ab, b23.y);
            }
        }
        __syncthreads();
    }

    #pragma unroll
    for (int i = 0; i < 8; i++) {
        int m = m0 + ty * 4 + (i < 4 ? i : 60 + i);
        float2 c0 = *reinterpret_cast<float2*>(&acc[i][0]);
        float2 c1 = *reinterpret_cast<float2*>(&acc[i][1]);
        float2 c2 = *reinterpret_cast<float2*>(&acc[i][2]);
        float2 c3 = *reinterpret_cast<float2*>(&acc[i][3]);
        *reinterpret_cast<float4*>(&C[(size_t)m * N + n0 + tx * 4]) =
            make_float4(c0.x, c0.y, c1.x, c1.y);
        *reinterpret_cast<float4*>(&C[(size_t)m * N + n0 + 64 + tx * 4]) =
            make_float4(c2.x, c2.y, c3.x, c3.y);
        __nv_bfloat162 p0 = __floats2bfloat162_rn(c0.x, c0.y);
        __nv_bfloat162 p1 = __floats2bfloat162_rn(c1.x, c1.y);
        __nv_bfloat162 p2 = __floats2bfloat162_rn(c2.x, c2.y);
        __nv_bfloat162 p3 = __floats2bfloat162_rn(c3.x, c3.y);
        *reinterpret_cast<__nv_bfloat162*>(&Cbf[(size_t)m * N + n0 + tx * 4]) = p0;
        *reinterpret_cast<__nv_bfloat162*>(&Cbf[(size_t)m * N + n0 + tx * 4 + 2]) = p1;
        *reinterpret_cast<__nv_bfloat162*>(&Cbf[(size_t)m * N + n0 + 64 + tx * 4]) = p2;
        *reinterpret_cast<__nv_bfloat162*>(&Cbf[(size_t)m * N + n0 + 64 + tx * 4 + 2]) = p3;
    }
}

// ---------------------------------------------------------------------------
// keys fp32 -> bf16
// ---------------------------------------------------------------------------
__global__ __launch_bounds__(256) void cvt_keys_kernel(const float* __restrict__ src)
{
    __nv_bfloat16* __restrict__ dst = (__nv_bfloat16*)g_kbf;
    size_t i = (size_t)blockIdx.x * 256 + threadIdx.x;   // float4 index
    float4 v = reinterpret_cast<const float4*>(src)[i];
    __nv_bfloat162 p0 = __floats2bfloat162_rn(v.x, v.y);
    __nv_bfloat162 p1 = __floats2bfloat162_rn(v.z, v.w);
    __nv_bfloat162* dp = reinterpret_cast<__nv_bfloat162*>(dst) + 2 * i;
    dp[0] = p0; dp[1] = p1;
}

// ---------------------------------------------------------------------------
// approx scores = q_bf @ keys_bf^T via mma.sync -> bf16 + per-block maxima.
// Tile 128x256, BK=32, 2-stage double buffer, 8 warps as 2(m)x4(n) = 64x64.
// (unchanged from R13 — bit-identical scores + blockmaxes)
// ---------------------------------------------------------------------------
#define TM2 128
#define TN2 256
#define BKS 32
#define A_STG 8192            // bytes per A stage (128 rows x 64B)
#define B_STG 16384           // bytes per B stage (256 rows x 64B)

__global__ __launch_bounds__(256, 1) void scores_mma_kernel()
{
    __shared__ __align__(16) unsigned char sA[2 * A_STG];   // 16 KB
    __shared__ __align__(16) unsigned char sB[2 * B_STG];   // 32 KB

    const int tid = threadIdx.x;
    const int wid = tid >> 5;
    const int lid = tid & 31;
    const int m0 = blockIdx.x * TM2;
    const int n0 = blockIdx.y * TN2;

    const int base_m = (wid & 1) * 64;
    const int warp_n = wid >> 1;           // 0..3
    const int base_n = warp_n * 64;

    const uint32_t aA = smem_u32(sA), aB = smem_u32(sB);

    const int rA0 = tid >> 2,          cA0 = tid & 3;
    const int rA1 = (tid + 256) >> 2,  cA1 = tid & 3;
    const uint32_t dA0 = rA0 * 64 + ((cA0 ^ ((rA0 >> 1) & 3)) << 4);
    const uint32_t dA1 = rA1 * 64 + ((cA1 ^ ((rA1 >> 1) & 3)) << 4);
    const size_t sA0 = (size_t)(m0 + rA0) * DDIM + cA0 * 8;
    const size_t sA1 = (size_t)(m0 + rA1) * DDIM + cA1 * 8;
    uint32_t dB[4]; size_t sBo[4];
    #pragma unroll
    for (int j = 0; j < 4; j++) {
        int cc = tid + j * 256;
        int rB = cc >> 2, cB = cc & 3;
        dB[j] = rB * 64 + ((cB ^ ((rB >> 1) & 3)) << 4);
        sBo[j] = (size_t)(n0 + rB) * DDIM + cB * 8;
    }

    const int aRow = base_m + (lid & 7) + ((lid >> 3) & 1) * 8;
    const int aSw  = (aRow >> 1) & 3;
    const int aChBase = (lid >> 4);            // 0/1
    const int bRow = base_n + (lid & 7) + ((lid >= 16) ? 8 : 0);
    const int bSw  = (bRow >> 1) & 3;
    const int bChBase = (lid >> 3) & 1;        // 0/1

    float c[4][8][4];
    #pragma unroll
    for (int i = 0; i < 4; i++)
        #pragma unroll
        for (int j = 0; j < 8; j++)
            #pragma unroll
            for (int k = 0; k < 4; k++) c[i][j][k] = 0.f;

    const int NKT = DDIM / BKS;  // 32

    cp16(aA + dA0, (const char*)g_qbf + sA0 * 2);
    cp16(aA + dA1, (const char*)g_qbf + sA1 * 2);
    #pragma unroll
    for (int j = 0; j < 4; j++)
        cp16(aB + dB[j], (const char*)g_kbf + sBo[j] * 2);
    cp_commit();

    for (int kt = 0; kt < NKT; kt++) {
        if (kt + 1 < NKT) {
            const uint32_t soA = ((kt + 1) & 1) * A_STG;
            const uint32_t soB = ((kt + 1) & 1) * B_STG;
            const size_t ko = (size_t)(kt + 1) * BKS;
            cp16(aA + soA + dA0, (const char*)g_qbf + (sA0 + ko) * 2);
            cp16(aA + soA + dA1, (const char*)g_qbf + (sA1 + ko) * 2);
            #pragma unroll
            for (int j = 0; j < 4; j++)
                cp16(aB + soB + dB[j], (const char*)g_kbf + (sBo[j] + ko) * 2);
        }
        cp_commit();
        cp_wait<1>();
        __syncthreads();

        const uint32_t soA = (kt & 1) * A_STG;
        const uint32_t soB = (kt & 1) * B_STG;
        #pragma unroll
        for (int kk = 0; kk < 2; kk++) {      // k ascending within stage
            uint32_t ah[4][4], bh[4][4];
            const int aCh = ((kk * 2 + aChBase) ^ aSw) << 4;
            const int bCh = ((kk * 2 + bChBase) ^ bSw) << 4;
            #pragma unroll
            for (int mf = 0; mf < 4; mf++)
                ldm_x4(ah[mf], aA + soA + (uint32_t)(aRow + mf * 16) * 64 + aCh);
            #pragma unroll
            for (int np = 0; np < 4; np++)
                ldm_x4(bh[np], aB + soB + (uint32_t)(bRow + np * 16) * 64 + bCh);
            #pragma unroll
            for (int mf = 0; mf < 4; mf++)
                #pragma unroll
                for (int nf = 0; nf < 8; nf++)
                    mma_bf16(c[mf][nf], ah[mf], &bh[nf >> 1][(nf & 1) * 2]);
        }
        __syncthreads();
    }

    const int crow = lid >> 2;
    const int ccol = (lid & 3) * 2;

    // ---- per-row block max (warp covers 64 rows x 64 cols) -> smem
    float* rmax = reinterpret_cast<float*>(sA);   // 128 rows x 4 warp_n
    #pragma unroll
    for (int mf = 0; mf < 4; mf++) {
        float fm0 = -INFINITY, fm1 = -INFINITY;
        #pragma unroll
        for (int nf = 0; nf < 8; nf++) {
            fm0 = fmaxf(fm0, fmaxf(c[mf][nf][0], c[mf][nf][1]));
            fm1 = fmaxf(fm1, fmaxf(c[mf][nf][2], c[mf][nf][3]));
        }
        fm0 = fmaxf(fm0, __shfl_xor_sync(0xffffffffu, fm0, 1));
        fm0 = fmaxf(fm0, __shfl_xor_sync(0xffffffffu, fm0, 2));
        fm1 = fmaxf(fm1, __shfl_xor_sync(0xffffffffu, fm1, 1));
        fm1 = fmaxf(fm1, __shfl_xor_sync(0xffffffffu, fm1, 2));
        if ((lid & 3) == 0) {
            rmax[(base_m + mf * 16 + crow) * 4 + warp_n] = fm0;
            rmax[(base_m + mf * 16 + crow + 8) * 4 + warp_n] = fm1;
        }
    }
    __syncthreads();
    if (tid < 128) {
        float v0 = fmaxf(rmax[tid * 4 + 0], rmax[tid * 4 + 1]);   // cols 0..127
        float v1 = fmaxf(rmax[tid * 4 + 2], rmax[tid * 4 + 3]);   // cols 128..255
        __nv_bfloat16 b0 = __float2bfloat16(v0);
        __nv_bfloat16 b1 = __float2bfloat16(v1);
        g_bmax[(size_t)(m0 + tid) * NBLK + blockIdx.y * 2 + 0] =
            *reinterpret_cast<unsigned short*>(&b0);
        g_bmax[(size_t)(m0 + tid) * NBLK + blockIdx.y * 2 + 1] =
            *reinterpret_cast<unsigned short*>(&b1);
    }

    // ---- bf16 scores
    #pragma unroll
    for (int mf = 0; mf < 4; mf++) {
        #pragma unroll
        for (int nf = 0; nf < 8; nf++) {
            int m = m0 + base_m + mf * 16 + crow;
            int n = n0 + base_n + nf * 8 + ccol;
            *reinterpret_cast<__nv_bfloat162*>(&g_sbf[(size_t)m * NKEY + n]) =
                __floats2bfloat162_rn(c[mf][nf][0], c[mf][nf][1]);
            *reinterpret_cast<__nv_bfloat162*>(&g_sbf[(size_t)(m + 8) * NKEY + n]) =
                __floats2bfloat162_rn(c[mf][nf][2], c[mf][nf][3]);
        }
    }
}

// ---------------------------------------------------------------------------
// Per-row topk (256 thr): blockmax rank -> thr -> scan selected blocks ->
// rank-based top-48 (value desc, lower index first) -> STAGED BIT-EXACT
// rescore (coalesced smem staging; sequential rn-fma chain, k ascending)
// -> exact rank -> softmax -> gather.
// ---------------------------------------------------------------------------
__global__ __launch_bounds__(256) void topk_out_kernel(
    const float* __restrict__ keys, const float* __restrict__ values,
    float* __restrict__ out)
{
    __shared__ float bmaxv[NBLK];                 // 2 KB
    __shared__ int   blist[NBLK];                 // 2 KB
    __shared__ float cbufV[CAP2];                 // 3 KB
    __shared__ int   cbufI[CAP2];                 // 3 KB
    __shared__ __align__(16) float qrow[DDIM];    // 4 KB
    __shared__ float kbuf[64 * 49];               // 12.25 KB (transposed, pad 49)
    __shared__ float gthr;
    __shared__ int   bcnt_s, scnt;
    __shared__ int   ci[NCAND];
    __shared__ float rs[NCAND];
    __shared__ int   sidx[KSEL];
    __shared__ float ssc[KSEL];
    __shared__ float sw[KSEL];
    __shared__ float sZ;

    const int tid = threadIdx.x;
    const int row = blockIdx.x;
    const __nv_bfloat16* srow = (const __nv_bfloat16*)g_sbf + (size_t)row * NKEY;

    // q row (fp32) for rescoring
    #pragma unroll
    for (int j = tid; j < DDIM / 4; j += 256)
        reinterpret_cast<float4*>(qrow)[j] =
            reinterpret_cast<const float4*>((const float*)g_q + (size_t)row * DDIM)[j];

    // ---- phase A: blockmax load + rank-based 48th-largest threshold
    #pragma unroll
    for (int j = tid; j < NBLK; j += 256) {
        uint32_t r = (uint32_t)g_bmax[(size_t)row * NBLK + j];
        bmaxv[j] = __uint_as_float(r << 16);
    }
    if (tid == 0) { bcnt_s = 0; scnt = 0; }
    if (tid < NCAND) ci[tid] = tid;   // defensive init (overwritten below)
    __syncthreads();

    {
        float v0 = bmaxv[tid], v1 = bmaxv[tid + 256];
        int r0 = 0, r1 = 0;
        for (int j = 0; j < NBLK; j++) {
            float v = bmaxv[j];                      // broadcast read
            r0 += (v > v0) || (v == v0 && j < tid);
            r1 += (v > v1) || (v == v1 && j < tid + 256);
        }
        if (r0 == NCAND - 1) gthr = v0;
        if (r1 == NCAND - 1) gthr = v1;
    }
    __syncthreads();
    const float thr = gthr;

    // selected block list (membership deterministic; order irrelevant)
    for (int j = tid; j < NBLK; j += 256)
        if (bmaxv[j] >= thr) { int p = atomicAdd(&bcnt_s, 1); blist[p] = j; }
    __syncthreads();
    const int bcnt = bcnt_s;

    // ---- phase B: scan only selected blocks, append keys >= thr
    for (int cch = tid; cch < bcnt * 16; cch += 256) {
        int b  = blist[cch >> 4];
        int ch = cch & 15;
        int base = b * 128 + ch * 8;
        uint4 raw = *reinterpret_cast<const uint4*>(srow + base);
        uint32_t ws[4] = {raw.x, raw.y, raw.z, raw.w};
        #pragma unroll
        for (int h = 0; h < 4; h++) {
            #pragma unroll
            for (int e = 0; e < 2; e++) {
                float v = __uint_as_float(e == 0 ? (ws[h] << 16)
                                                 : (ws[h] & 0xffff0000u));
                if (v >= thr) {
                    int pos = atomicAdd(&scnt, 1);
                    if (pos < CAP2) { cbufV[pos] = v; cbufI[pos] = base + h * 2 + e; }
                }
            }
        }
    }
    __syncthreads();
    const int m = min(scnt, CAP2);

    // ---- phase C: rank-based top-48 (value desc, lower index tiebreak)
    for (int base = 0; base < m; base += 256) {
        int idx = base + tid;
        bool valid = idx < m;
        float mv = valid ? cbufV[idx] : 0.f;
        int   mi = valid ? cbufI[idx] : 0;
        int rank = 0;
        for (int j = 0; j < m; j++) {
            float v = cbufV[j];                      // broadcast read
            int  ix = cbufI[j];
            rank += (v > mv) || (v == mv && ix < mi);
        }
        if (valid && rank < NCAND) ci[rank] = mi;
    }
    __syncthreads();

    // ---- phase D: staged BIT-EXACT rescore
    // Stage 48 candidate rows in 16 chunks of 64 k into transposed smem
    // (kbuf[kk][cand], stride 49 -> conflict-free chain reads), coalesced
    // float4 global loads, register double-buffered across chunks.
    float4 pre[3];
    #pragma unroll
    for (int it = 0; it < 3; it++) {
        int j = tid + it * 256;
        int r = j >> 4, kk4 = j & 15;
        pre[it] = *reinterpret_cast<const float4*>(
            keys + (size_t)ci[r] * DDIM + kk4 * 4);
    }
    float acc = 0.f;
    for (int cch = 0; cch < 16; cch++) {
        __syncthreads();                 // prior chunk's compute done
        #pragma unroll
        for (int it = 0; it < 3; it++) {
            int j = tid + it * 256;
            int r = j >> 4, kb = (j & 15) * 4;
            kbuf[(kb + 0) * 49 + r] = pre[it].x;
            kbuf[(kb + 1) * 49 + r] = pre[it].y;
            kbuf[(kb + 2) * 49 + r] = pre[it].z;
            kbuf[(kb + 3) * 49 + r] = pre[it].w;
        }
        __syncthreads();
        if (cch + 1 < 16) {
            #pragma unroll
            for (int it = 0; it < 3; it++) {
                int j = tid + it * 256;
                int r = j >> 4, kk4 = j & 15;
                pre[it] = *reinterpret_cast<const float4*>(
                    keys + (size_t)ci[r] * DDIM + (cch + 1) * 64 + kk4 * 4);
            }
        }
        if (tid < NCAND) {
            #pragma unroll
            for (int kk = 0; kk < 64; kk++)
                acc = __fmaf_rn(qrow[cch * 64 + kk], kbuf[kk * 49 + tid], acc);
        }
    }
    if (tid < NCAND) rs[tid] = acc;
    __syncthreads();

    // ---- phase E: exact rank (lower-index tie-break); select top-32
    if (tid < NCAND) {
        float sc = rs[tid];
        int   myi = ci[tid];
        int rank = 0;
        #pragma unroll
        for (int j = 0; j < NCAND; j++) {
            float sj = rs[j];
            rank += (sj > sc) || (sj == sc && ci[j] < myi);
        }
        if (rank < KSEL) { sidx[rank] = myi; ssc[rank] = sc; }
    }
    __syncthreads();

    // softmax over exact top-32 (TEMP=1); ssc[0] is the max
    if (tid < KSEL) sw[tid] = expf(ssc[tid] - ssc[0]);
    __syncthreads();
    if (tid == 0) {
        float z = 0.f;
        #pragma unroll
        for (int j = 0; j < KSEL; j++) z += sw[j];
        sZ = z;
    }
    __syncthreads();
    const float invZ = 1.0f / sZ;

    // weighted gather of values rows (GATING=1)
    for (int d = tid; d < DDIM; d += 256) {
        float acc2 = 0.f;
        #pragma unroll 8
        for (int k = 0; k < KSEL; k++)
            acc2 += sw[k] * values[(size_t)sidx[k] * DDIM + d];
        out[(size_t)row * DDIM + d] = acc2 * invZ;
    }
}

// ---------------------------------------------------------------------------
extern "C" void kernel_launch(void* const* d_in, const int* in_sizes, int n_in,
                              void* d_out, int out_size) {
    const float* x      = (const float*)d_in[0];
    const float* q_w    = (const float*)d_in[1];
    const float* keys   = (const float*)d_in[2];
    const float* values = (const float*)d_in[3];
    float* out = (float*)d_out;

    cudaStream_t st = cudaStreamPerThread;

    // 1) q = x @ q_w^T -> g_q (fp32) + g_qbf (bf16 mirror)
    dim3 g1(NROWS / BM, DDIM / BN);
    gemm_qproj_kernel<<<g1, 256, 0, st>>>(x, q_w, NROWS, DDIM, DDIM);

    // 2) keys -> bf16
    cvt_keys_kernel<<<(int)(((size_t)NKEY * DDIM / 4) / 256), 256, 0, st>>>(keys);

    // 3) approx scores + per-block maxima via bf16 mma (128x256 tiles)
    dim3 g2(NROWS / TM2, NKEY / TN2);
    scores_mma_kernel<<<g2, 256, 0, st>>>();

    // 4) blockmax-filtered candidates + staged bit-exact rescore + gather
    topk_out_kernel<<<NROWS, 256, 0, st>>>(keys, values, out);
}